// round 9
// baseline (speedup 1.0000x reference)
#include <cuda_runtime.h>
#include <math.h>
#include <stdint.h>

#define BS 32
#define NS 65536
#define NF 128
#define CHUNK 8
#define NCH (NS / CHUNK)      // 8192
#define SRf 48000.0f
#define STAB 0.999f
#define POSC (127.0f / 65535.0f)

// Output plane offsets (elements of BS*NS):
// dry=0, wet=1, env=2, y_ab=3, a_coeff3=4..6, b_coeff=7..9, y_a=10

struct BParam {
    float inc, phase, kk, shp;
    float sm, gain, dur, alpha;
    float dist, pad0, pad1, pad2;
};

__device__ BParam g_bp[BS];
__device__ float4 g_frame[BS * NF * 2];   // per frame: {a1,a2,b0,b1},{b2,-,-,-}
__device__ float  g_chunk[BS * NCH * 6];  // u1,v1,u2,v2,yp1,yp2
__device__ float2 g_init[BS * NCH];

// ---- XLA rational tanh (Eigen fast tanh) ----
__device__ __forceinline__ float xla_tanh(float x) {
    const float kClamp = 7.90531110763549805f;
    float xc = fminf(fmaxf(x, -kClamp), kClamp);
    float x2 = __fmul_rn(xc, xc);
    float p = __fadd_rn(2.00018790482477e-13f, __fmul_rn(x2, -2.76076847742355e-16f));
    p = __fadd_rn(-8.60467152213735e-11f, __fmul_rn(x2, p));
    p = __fadd_rn(5.12229709037114e-08f,  __fmul_rn(x2, p));
    p = __fadd_rn(1.48572235717979e-05f,  __fmul_rn(x2, p));
    p = __fadd_rn(6.37261928875436e-04f,  __fmul_rn(x2, p));
    p = __fadd_rn(4.89352455891786e-03f,  __fmul_rn(x2, p));
    float num = __fmul_rn(xc, p);
    float q = __fadd_rn(1.18534705686654e-04f, __fmul_rn(x2, 1.19825839466702e-06f));
    q = __fadd_rn(2.26843463243900e-03f, __fmul_rn(x2, q));
    q = __fadd_rn(4.89352518554385e-03f, __fmul_rn(x2, q));
    float r = __fdiv_rn(num, q);
    return (fabsf(x) < 0.0004f) ? x : r;
}

// ---- XLA-CPU-style sin/cos: range reduce with single-f32 2*pi, then accurate ----
__device__ __forceinline__ float xla_sin(float x) {
    float k = rintf(__fmul_rn(x, 0.15915494309189535f));
    float r = fmaf(-k, 6.28318548202514648f, x);
    return sinf(r);
}
__device__ __forceinline__ float xla_cos(float x) {
    float k = rintf(__fmul_rn(x, 0.15915494309189535f));
    float r = fmaf(-k, 6.28318548202514648f, x);
    return cosf(r);
}

// Chain over bits >=3 of v (v multiple of 8, v>0): MSB->LSB rounded adds.
__device__ __forceinline__ float cum_base3(float c, unsigned v) {
    int msb = 31 - __clz(v);
    float r = c * __int_as_float((127 + msb) << 23);
#pragma unroll 1
    for (int k = msb - 1; k >= 3; k--) {
        if ((v >> k) & 1u)
            r = __fadd_rn(r, c * __int_as_float((127 + k) << 23));
    }
    return r;
}

// ---------------- K0 ----------------
__global__ void k_prep(const float* __restrict__ f0_hz,
                       const float* __restrict__ durp,
                       const float* __restrict__ phasep,
                       const float* __restrict__ logits,
                       const float* __restrict__ shpp,
                       const float* __restrict__ gainp,
                       const float* __restrict__ distp,
                       const float* __restrict__ alphap) {
    int tid = blockIdx.x * blockDim.x + threadIdx.x;
    if (tid >= BS * NF) return;
    int b = tid / NF;
    int f = tid - b * NF;
    const float* lg = logits + (size_t)tid * 5;
    float th0 = xla_tanh(lg[0]);
    float a1 = __fmul_rn(__fmul_rn(2.0f, th0), STAB);
    float a1a = fabsf(a1);
    float th1 = xla_tanh(lg[1]);
    float a2 = __fdiv_rn(__fadd_rn(__fmul_rn(__fmul_rn(__fsub_rn(2.0f, a1a), th1), STAB), a1a), 2.0f);
    g_frame[tid * 2]     = make_float4(a1, a2, lg[2], lg[3]);
    g_frame[tid * 2 + 1] = make_float4(lg[4], 0.f, 0.f, 0.f);
    if (f == 0) {
        BParam p;
        float f0 = f0_hz[b];
        p.inc = __fdiv_rn(f0, SRf);
        p.phase = phasep[b];
        float partials = __fdiv_rn(12000.0f, __fmul_rn(f0, log10f(f0)));
        p.kk = __fmul_rn(3.14159274101257324f, partials);
        p.shp = shpp[b];
        p.sm = __fsub_rn(1.0f, __fmul_rn(shpp[b], 0.5f));
        p.gain = gainp[b];
        p.dur = durp[b];
        p.alpha = alphap[b];
        p.dist = distp[b];
        g_bp[b] = p;
    }
}

// interp helper operating on preselected scalars (bit-identical formula)
#define INTERP(dst, fv, gv) dst = __fadd_rn(__fmul_rn(fv, w0), __fmul_rn(gv, frc))

// ---------------- K1: osc + env + coeff interp + fused pass1 ----------------
__global__ void k_mainp1(float* __restrict__ out) {
    int tid = blockIdx.x * blockDim.x + threadIdx.x;
    if (tid >= BS * NCH) return;
    int b = tid >> 13;
    int c = tid & (NCH - 1);
    int s0 = c << 3;
    BParam p = g_bp[b];

    float pos0 = __fmul_rn((float)s0, POSC);
    int i0s = (int)floorf(pos0);
    i0s = min(i0s, 126);
    float i0sf = (float)i0s;
    int i2x = min(i0s + 2, 127);
    float4 F0a = g_frame[(b * NF + i0s) * 2],     F0b = g_frame[(b * NF + i0s) * 2 + 1];
    float4 F1a = g_frame[(b * NF + i0s + 1) * 2], F1b = g_frame[(b * NF + i0s + 1) * 2 + 1];

    // uniform-segment test: last sample's i0 equals first's?
    float posL = __fmul_rn((float)(s0 + 7), POSC);
    int i0L = min((int)floorf(posL), 126);
    bool uniform = (i0L == i0s);

    float yp1 = 0.f, yp2 = 0.f, u1 = 1.f, u2 = 0.f, v1 = 0.f, v2 = 1.f;
    float dryv[8], envv[8], a1v[8], a2v[8], b0v[8], b1v[8], b2v[8];

    float tt0 = __fdiv_rn((float)s0, SRf);
    bool alive = (tt0 <= p.dur);

    if (alive) {
        float inc = p.inc;
        float i4 = inc * 4.0f, i2 = inc * 2.0f;
        float baseA = (s0 == 0) ? 0.0f : cum_base3(inc, (unsigned)s0);
        float baseB = cum_base3(inc, (unsigned)(s0 + 8));
#pragma unroll
        for (int j = 0; j < 8; j++) {
            int i = s0 + j;
            unsigned l = (unsigned)(j + 1);
            float cum = (l < 8u) ? baseA : baseB;
            if (l & 4u)  cum = __fadd_rn(cum, i4);
            if (l & 2u)  cum = __fadd_rn(cum, i2);
            if (l & 1u)  cum = __fadd_rn(cum, inc);
            float arg = __fadd_rn(__fmul_rn(6.28318548202514648f, cum), p.phase);
            float s = xla_sin(arg);
            float cc = xla_cos(__fmul_rn(arg, 0.5f));
            float sq = xla_tanh(__fmul_rn(__fmul_rn(p.kk, s), 0.5f));
            float vco = __fmul_rn(__fmul_rn(p.sm, sq),
                                  __fadd_rn(1.0f, __fmul_rn(p.shp, cc)));

            float tt = __fdiv_rn((float)i, SRf);
            float ramp = __fsub_rn(1.0f, __fdiv_rn(tt, p.dur));
            ramp = fminf(fmaxf(ramp, 0.001f), 1.0f);
            float env = __powf(ramp, p.alpha);
            if (!(tt <= p.dur)) env = 0.0f;
            envv[j] = env;
            dryv[j] = __fmul_rn(__fmul_rn(vco, p.gain), env);
        }
    } else {
#pragma unroll
        for (int j = 0; j < 8; j++) { envv[j] = 0.0f; dryv[j] = 0.0f; }
    }

    if (uniform) {
        float fa1 = F0a.x, fa2 = F0a.y, fb0 = F0a.z, fb1 = F0a.w, fb2 = F0b.x;
        float ga1 = F1a.x, ga2 = F1a.y, gb0 = F1a.z, gb1 = F1a.w, gb2 = F1b.x;
#pragma unroll
        for (int j = 0; j < 8; j++) {
            float pos = __fmul_rn((float)(s0 + j), POSC);
            float frc = __fsub_rn(pos, i0sf);
            float w0 = __fsub_rn(1.0f, frc);
            float a1, a2;
            INTERP(a1, fa1, ga1); INTERP(a2, fa2, ga2);
            a1v[j] = a1; a2v[j] = a2;
            INTERP(b0v[j], fb0, gb0); INTERP(b1v[j], fb1, gb1); INTERP(b2v[j], fb2, gb2);

            float yp = fmaf(-a1, yp1, fmaf(-a2, yp2, dryv[j]));
            float uu = fmaf(-a1, u1, -(a2 * u2));
            float vv = fmaf(-a1, v1, -(a2 * v2));
            yp2 = yp1; yp1 = yp;
            u2 = u1; u1 = uu;
            v2 = v1; v1 = vv;
        }
    } else {
        float4 F2a = g_frame[(b * NF + i2x) * 2], F2b = g_frame[(b * NF + i2x) * 2 + 1];
#pragma unroll
        for (int j = 0; j < 8; j++) {
            float pos = __fmul_rn((float)(s0 + j), POSC);
            int i0 = min((int)floorf(pos), 126);
            float frc = __fsub_rn(pos, (float)i0);
            float w0 = __fsub_rn(1.0f, frc);
            bool hi = (i0 != i0s);
            float fa1 = hi ? F1a.x : F0a.x, ga1 = hi ? F2a.x : F1a.x;
            float fa2 = hi ? F1a.y : F0a.y, ga2 = hi ? F2a.y : F1a.y;
            float fb0 = hi ? F1a.z : F0a.z, gb0 = hi ? F2a.z : F1a.z;
            float fb1 = hi ? F1a.w : F0a.w, gb1 = hi ? F2a.w : F1a.w;
            float fb2 = hi ? F1b.x : F0b.x, gb2 = hi ? F2b.x : F1b.x;
            float a1, a2;
            INTERP(a1, fa1, ga1); INTERP(a2, fa2, ga2);
            a1v[j] = a1; a2v[j] = a2;
            INTERP(b0v[j], fb0, gb0); INTERP(b1v[j], fb1, gb1); INTERP(b2v[j], fb2, gb2);

            float yp = fmaf(-a1, yp1, fmaf(-a2, yp2, dryv[j]));
            float uu = fmaf(-a1, u1, -(a2 * u2));
            float vv = fmaf(-a1, v1, -(a2 * v2));
            yp2 = yp1; yp1 = yp;
            u2 = u1; u1 = uu;
            v2 = v1; v1 = vv;
        }
    }

    size_t base = (size_t)b * NS + s0;
    float4* dptr = (float4*)(out + base);
    dptr[0] = make_float4(dryv[0], dryv[1], dryv[2], dryv[3]);
    dptr[1] = make_float4(dryv[4], dryv[5], dryv[6], dryv[7]);
    float4* eptr = (float4*)(out + 2ull * BS * NS + base);
    eptr[0] = make_float4(envv[0], envv[1], envv[2], envv[3]);
    eptr[1] = make_float4(envv[4], envv[5], envv[6], envv[7]);
    float4* aptr = (float4*)(out + 4ull * BS * NS + base * 3);
    aptr[0] = make_float4(1.0f, a1v[0], a2v[0], 1.0f);
    aptr[1] = make_float4(a1v[1], a2v[1], 1.0f, a1v[2]);
    aptr[2] = make_float4(a2v[2], 1.0f, a1v[3], a2v[3]);
    aptr[3] = make_float4(1.0f, a1v[4], a2v[4], 1.0f);
    aptr[4] = make_float4(a1v[5], a2v[5], 1.0f, a1v[6]);
    aptr[5] = make_float4(a2v[6], 1.0f, a1v[7], a2v[7]);
    float4* bptr = (float4*)(out + 7ull * BS * NS + base * 3);
    bptr[0] = make_float4(b0v[0], b1v[0], b2v[0], b0v[1]);
    bptr[1] = make_float4(b1v[1], b2v[1], b0v[2], b1v[2]);
    bptr[2] = make_float4(b2v[2], b0v[3], b1v[3], b2v[3]);
    bptr[3] = make_float4(b0v[4], b1v[4], b2v[4], b0v[5]);
    bptr[4] = make_float4(b1v[5], b2v[5], b0v[6], b1v[6]);
    bptr[5] = make_float4(b2v[6], b0v[7], b1v[7], b2v[7]);

    float* o = g_chunk + (size_t)tid * 6;
    o[0] = u1; o[1] = v1; o[2] = u2; o[3] = v2; o[4] = yp1; o[5] = yp2;
}

// ---------------- K2: per-voice affine scan (dynamic smem staged) ----------------
__global__ void k_scan2() {
    extern __shared__ float sm[];      // NCH*7 floats, stride-7 records
    int b = blockIdx.x;
    const float* raw = g_chunk + (size_t)b * NCH * 6;
    const int G = NCH / 32;            // 256 chunks per lane
    for (int idx = threadIdx.x; idx < NCH * 6; idx += blockDim.x) {
        int chunk = idx / 6;
        int f = idx - chunk * 6;
        int lane = chunk / G;
        int cpos = chunk - lane * G;
        sm[(cpos * 32 + lane) * 7 + f] = raw[idx];
    }
    __syncthreads();
    if (threadIdx.x < 32) {
        int lane = threadIdx.x;

        float m00 = 1.f, m01 = 0.f, m10 = 0.f, m11 = 1.f, p0 = 0.f, p1 = 0.f;
#pragma unroll 1
        for (int c = 0; c < G; c++) {
            const float* rec = &sm[(c * 32 + lane) * 7];
            float c00 = rec[0], c01 = rec[1], c10 = rec[2], c11 = rec[3], r0 = rec[4], r1 = rec[5];
            float n00 = __fmaf_rn(c00, m00, __fmul_rn(c01, m10));
            float n01 = __fmaf_rn(c00, m01, __fmul_rn(c01, m11));
            float n10 = __fmaf_rn(c10, m00, __fmul_rn(c11, m10));
            float n11 = __fmaf_rn(c10, m01, __fmul_rn(c11, m11));
            float np0 = __fadd_rn(__fmaf_rn(c00, p0, __fmul_rn(c01, p1)), r0);
            float np1 = __fadd_rn(__fmaf_rn(c10, p0, __fmul_rn(c11, p1)), r1);
            m00 = n00; m01 = n01; m10 = n10; m11 = n11; p0 = np0; p1 = np1;
        }
#pragma unroll
        for (int d = 1; d < 32; d <<= 1) {
            float e00 = __shfl_up_sync(0xffffffffu, m00, d);
            float e01 = __shfl_up_sync(0xffffffffu, m01, d);
            float e10 = __shfl_up_sync(0xffffffffu, m10, d);
            float e11 = __shfl_up_sync(0xffffffffu, m11, d);
            float ep0 = __shfl_up_sync(0xffffffffu, p0, d);
            float ep1 = __shfl_up_sync(0xffffffffu, p1, d);
            if (lane >= d) {
                float n00 = __fmaf_rn(m00, e00, __fmul_rn(m01, e10));
                float n01 = __fmaf_rn(m00, e01, __fmul_rn(m01, e11));
                float n10 = __fmaf_rn(m10, e00, __fmul_rn(m11, e10));
                float n11 = __fmaf_rn(m10, e01, __fmul_rn(m11, e11));
                float np0 = __fadd_rn(__fmaf_rn(m00, ep0, __fmul_rn(m01, ep1)), p0);
                float np1 = __fadd_rn(__fmaf_rn(m10, ep0, __fmul_rn(m11, ep1)), p1);
                m00 = n00; m01 = n01; m10 = n10; m11 = n11; p0 = np0; p1 = np1;
            }
        }
        float s0 = __shfl_up_sync(0xffffffffu, p0, 1);
        float s1 = __shfl_up_sync(0xffffffffu, p1, 1);
        if (lane == 0) { s0 = 0.f; s1 = 0.f; }

#pragma unroll 1
        for (int c = 0; c < G; c++) {
            g_init[(size_t)b * NCH + lane * G + c] = make_float2(s0, s1);
            const float* rec = &sm[(c * 32 + lane) * 7];
            float c00 = rec[0], c01 = rec[1], c10 = rec[2], c11 = rec[3], r0 = rec[4], r1 = rec[5];
            float ns0 = __fadd_rn(__fmaf_rn(c00, s0, __fmul_rn(c01, s1)), r0);
            float ns1 = __fadd_rn(__fmaf_rn(c10, s0, __fmul_rn(c11, s1)), r1);
            s0 = ns0; s1 = ns1;
        }
    }
}

// ---------------- K3: pass 2 — coeff recompute + IIR + FIR + tanh ----------------
__global__ void k_pass2(float* __restrict__ out) {
    int tid = blockIdx.x * blockDim.x + threadIdx.x;
    if (tid >= BS * NCH) return;
    int b = tid >> 13;
    int c = tid & (NCH - 1);
    int s0 = c << 3;
    size_t base = (size_t)b * NS + s0;
    const float* dry = out + base;
    float* w_wet = out + 1ull * BS * NS + base;
    float* w_yab = out + 3ull * BS * NS + base;
    float* w_ya = out + 10ull * BS * NS + base;

    float pos0 = __fmul_rn((float)s0, POSC);
    int i0s = (int)floorf(pos0);
    i0s = min(i0s, 126);
    float i0sf = (float)i0s;
    int i2x = min(i0s + 2, 127);
    float4 F0a = g_frame[(b * NF + i0s) * 2],     F0b = g_frame[(b * NF + i0s) * 2 + 1];
    float4 F1a = g_frame[(b * NF + i0s + 1) * 2], F1b = g_frame[(b * NF + i0s + 1) * 2 + 1];

    float posL = __fmul_rn((float)(s0 + 7), POSC);
    int i0L = min((int)floorf(posL), 126);
    bool uniform = (i0L == i0s);

    float2 ini = g_init[tid];
    float y1 = ini.x, y2 = ini.y;
    float dg = g_bp[b].dist;

    float4 x0 = *(const float4*)(dry);
    float4 x1 = *(const float4*)(dry + 4);
    float xs[8] = {x0.x, x0.y, x0.z, x0.w, x1.x, x1.y, x1.z, x1.w};
    float ya[8], yb[8], wt[8];

    if (uniform) {
        float fa1 = F0a.x, fa2 = F0a.y, fb0 = F0a.z, fb1 = F0a.w, fb2 = F0b.x;
        float ga1 = F1a.x, ga2 = F1a.y, gb0 = F1a.z, gb1 = F1a.w, gb2 = F1b.x;
#pragma unroll
        for (int j = 0; j < 8; j++) {
            float pos = __fmul_rn((float)(s0 + j), POSC);
            float frc = __fsub_rn(pos, i0sf);
            float w0 = __fsub_rn(1.0f, frc);
            float a1, a2, c0, c1, c2;
            INTERP(a1, fa1, ga1); INTERP(a2, fa2, ga2);
            INTERP(c0, fb0, gb0); INTERP(c1, fb1, gb1); INTERP(c2, fb2, gb2);

            float y = __fsub_rn(__fsub_rn(xs[j], __fmul_rn(a1, y1)), __fmul_rn(a2, y2));
            float v = __fadd_rn(__fadd_rn(__fmul_rn(c0, y), __fmul_rn(c1, y1)),
                                __fmul_rn(c2, y2));
            ya[j] = y; yb[j] = v;
            wt[j] = xla_tanh(__fmul_rn(v, dg));
            y2 = y1; y1 = y;
        }
    } else {
        float4 F2a = g_frame[(b * NF + i2x) * 2], F2b = g_frame[(b * NF + i2x) * 2 + 1];
#pragma unroll
        for (int j = 0; j < 8; j++) {
            float pos = __fmul_rn((float)(s0 + j), POSC);
            int i0 = min((int)floorf(pos), 126);
            float frc = __fsub_rn(pos, (float)i0);
            float w0 = __fsub_rn(1.0f, frc);
            bool hi = (i0 != i0s);
            float fa1 = hi ? F1a.x : F0a.x, ga1 = hi ? F2a.x : F1a.x;
            float fa2 = hi ? F1a.y : F0a.y, ga2 = hi ? F2a.y : F1a.y;
            float fb0 = hi ? F1a.z : F0a.z, gb0 = hi ? F2a.z : F1a.z;
            float fb1 = hi ? F1a.w : F0a.w, gb1 = hi ? F2a.w : F1a.w;
            float fb2 = hi ? F1b.x : F0b.x, gb2 = hi ? F2b.x : F1b.x;
            float a1, a2, c0, c1, c2;
            INTERP(a1, fa1, ga1); INTERP(a2, fa2, ga2);
            INTERP(c0, fb0, gb0); INTERP(c1, fb1, gb1); INTERP(c2, fb2, gb2);

            float y = __fsub_rn(__fsub_rn(xs[j], __fmul_rn(a1, y1)), __fmul_rn(a2, y2));
            float v = __fadd_rn(__fadd_rn(__fmul_rn(c0, y), __fmul_rn(c1, y1)),
                                __fmul_rn(c2, y2));
            ya[j] = y; yb[j] = v;
            wt[j] = xla_tanh(__fmul_rn(v, dg));
            y2 = y1; y1 = y;
        }
    }
    ((float4*)w_ya)[0] = make_float4(ya[0], ya[1], ya[2], ya[3]);
    ((float4*)w_ya)[1] = make_float4(ya[4], ya[5], ya[6], ya[7]);
    ((float4*)w_yab)[0] = make_float4(yb[0], yb[1], yb[2], yb[3]);
    ((float4*)w_yab)[1] = make_float4(yb[4], yb[5], yb[6], yb[7]);
    ((float4*)w_wet)[0] = make_float4(wt[0], wt[1], wt[2], wt[3]);
    ((float4*)w_wet)[1] = make_float4(wt[4], wt[5], wt[6], wt[7]);
}

extern "C" void kernel_launch(void* const* d_in, const int* in_sizes, int n_in,
                              void* d_out, int out_size) {
    const float* f0_hz = (const float*)d_in[0];
    const float* note_on = (const float*)d_in[1];
    const float* phase = (const float*)d_in[2];
    const float* logits = (const float*)d_in[3];
    const float* osc_shape = (const float*)d_in[4];
    const float* osc_gain = (const float*)d_in[5];
    const float* dist_gain = (const float*)d_in[6];
    const float* learned_alpha = (const float*)d_in[7];
    float* out = (float*)d_out;

    static int smem_set = 0;
    const int scan_smem = NCH * 7 * sizeof(float);   // 229376 B
    if (!smem_set) {
        cudaFuncSetAttribute(k_scan2, cudaFuncAttributeMaxDynamicSharedMemorySize, scan_smem);
        smem_set = 1;
    }

    k_prep<<<(BS * NF + 255) / 256, 256>>>(f0_hz, note_on, phase, logits,
                                           osc_shape, osc_gain, dist_gain, learned_alpha);
    k_mainp1<<<(BS * NCH + 127) / 128, 128>>>(out);
    k_scan2<<<BS, 1024, scan_smem>>>();
    k_pass2<<<(BS * NCH + 127) / 128, 128>>>(out);
}

// round 10
// speedup vs baseline: 1.0580x; 1.0580x over previous
#include <cuda_runtime.h>
#include <math.h>
#include <stdint.h>

#define BS 32
#define NS 65536
#define NF 128
#define CHUNK 8
#define NCH (NS / CHUNK)      // 8192
#define SRf 48000.0f
#define STAB 0.999f
#define POSC (127.0f / 65535.0f)

// Output plane offsets (elements of BS*NS):
// dry=0, wet=1, env=2, y_ab=3, a_coeff3=4..6, b_coeff=7..9, y_a=10

struct BParam {
    float inc, phase, kk, shp;
    float sm, gain, dur, alpha;
    float dist, pad0, pad1, pad2;
};

__device__ BParam g_bp[BS];
__device__ float4 g_frame[BS * NF * 2];   // per frame: {a1,a2,b0,b1},{b2,-,-,-}
__device__ float  g_chunk[BS * NCH * 6];  // u1,v1,u2,v2,yp1,yp2
__device__ float2 g_init[BS * NCH];

// ---- XLA rational tanh (Eigen fast tanh) ----
__device__ __forceinline__ float xla_tanh(float x) {
    const float kClamp = 7.90531110763549805f;
    float xc = fminf(fmaxf(x, -kClamp), kClamp);
    float x2 = __fmul_rn(xc, xc);
    float p = __fadd_rn(2.00018790482477e-13f, __fmul_rn(x2, -2.76076847742355e-16f));
    p = __fadd_rn(-8.60467152213735e-11f, __fmul_rn(x2, p));
    p = __fadd_rn(5.12229709037114e-08f,  __fmul_rn(x2, p));
    p = __fadd_rn(1.48572235717979e-05f,  __fmul_rn(x2, p));
    p = __fadd_rn(6.37261928875436e-04f,  __fmul_rn(x2, p));
    p = __fadd_rn(4.89352455891786e-03f,  __fmul_rn(x2, p));
    float num = __fmul_rn(xc, p);
    float q = __fadd_rn(1.18534705686654e-04f, __fmul_rn(x2, 1.19825839466702e-06f));
    q = __fadd_rn(2.26843463243900e-03f, __fmul_rn(x2, q));
    q = __fadd_rn(4.89352518554385e-03f, __fmul_rn(x2, q));
    float r = __fdiv_rn(num, q);
    return (fabsf(x) < 0.0004f) ? x : r;
}

// ---- fast minimax sin/cos kernels for |r| <= ~pi (post 2pi-reduction) ----
// fdlibm-style: q = rint(r*2/pi) in {-2..2}; t = r - q*pi/2 (2-FMA split);
// 4-term polys on [-pi/4, pi/4]; quadrant select. |err| ~1 ulp.
__device__ __forceinline__ void fast_sc(float r, float& ps, float& pc, int& iq) {
    float qf = rintf(r * 0.636619772367581343f);
    float t = fmaf(qf, -1.57079637050628662109f, r);
    t = fmaf(qf, 4.37113900018624283e-8f, t);
    iq = ((int)qf) & 3;
    float t2 = t * t;
    float s = fmaf(t2, 2.7557314297e-06f, -1.9841270114e-04f);
    s = fmaf(t2, s, 8.3333337680e-03f);
    s = fmaf(t2, s, -1.6666667163e-01f);
    ps = fmaf(t * t2, s, t);
    float c = fmaf(t2, 2.4801587642e-05f, -1.3888889225e-03f);
    c = fmaf(t2, c, 4.1666667908e-02f);
    c = fmaf(t2, c, -0.5f);
    pc = fmaf(t2, c, 1.0f);
}
__device__ __forceinline__ float fast_sin(float r) {
    float ps, pc; int iq;
    fast_sc(r, ps, pc, iq);
    float v = (iq & 1) ? pc : ps;
    return (iq & 2) ? -v : v;
}
__device__ __forceinline__ float fast_cos(float r) {
    float ps, pc; int iq;
    fast_sc(r, ps, pc, iq);
    float v = (iq & 1) ? ps : pc;
    return ((iq + 1) & 2) ? -v : v;
}

// ---- XLA-CPU-style sin/cos: range reduce with single-f32 2*pi, then kernel ----
__device__ __forceinline__ float xla_sin(float x) {
    float k = rintf(__fmul_rn(x, 0.15915494309189535f));
    float r = fmaf(-k, 6.28318548202514648f, x);
    return fast_sin(r);
}
__device__ __forceinline__ float xla_cos(float x) {
    float k = rintf(__fmul_rn(x, 0.15915494309189535f));
    float r = fmaf(-k, 6.28318548202514648f, x);
    return fast_cos(r);
}

// Chain over bits >=3 of v (v multiple of 8, v>0): MSB->LSB rounded adds.
__device__ __forceinline__ float cum_base3(float c, unsigned v) {
    int msb = 31 - __clz(v);
    float r = c * __int_as_float((127 + msb) << 23);
#pragma unroll 1
    for (int k = msb - 1; k >= 3; k--) {
        if ((v >> k) & 1u)
            r = __fadd_rn(r, c * __int_as_float((127 + k) << 23));
    }
    return r;
}

// ---------------- K0 ----------------
__global__ void k_prep(const float* __restrict__ f0_hz,
                       const float* __restrict__ durp,
                       const float* __restrict__ phasep,
                       const float* __restrict__ logits,
                       const float* __restrict__ shpp,
                       const float* __restrict__ gainp,
                       const float* __restrict__ distp,
                       const float* __restrict__ alphap) {
    int tid = blockIdx.x * blockDim.x + threadIdx.x;
    if (tid >= BS * NF) return;
    int b = tid / NF;
    int f = tid - b * NF;
    const float* lg = logits + (size_t)tid * 5;
    float th0 = xla_tanh(lg[0]);
    float a1 = __fmul_rn(__fmul_rn(2.0f, th0), STAB);
    float a1a = fabsf(a1);
    float th1 = xla_tanh(lg[1]);
    float a2 = __fdiv_rn(__fadd_rn(__fmul_rn(__fmul_rn(__fsub_rn(2.0f, a1a), th1), STAB), a1a), 2.0f);
    g_frame[tid * 2]     = make_float4(a1, a2, lg[2], lg[3]);
    g_frame[tid * 2 + 1] = make_float4(lg[4], 0.f, 0.f, 0.f);
    if (f == 0) {
        BParam p;
        float f0 = f0_hz[b];
        p.inc = __fdiv_rn(f0, SRf);
        p.phase = phasep[b];
        float partials = __fdiv_rn(12000.0f, __fmul_rn(f0, log10f(f0)));
        p.kk = __fmul_rn(3.14159274101257324f, partials);
        p.shp = shpp[b];
        p.sm = __fsub_rn(1.0f, __fmul_rn(shpp[b], 0.5f));
        p.gain = gainp[b];
        p.dur = durp[b];
        p.alpha = alphap[b];
        p.dist = distp[b];
        g_bp[b] = p;
    }
}

// ---------------- K1: osc + env + coeff interp + fused pass1 (R8 structure) ----------------
__global__ void k_mainp1(float* __restrict__ out) {
    int tid = blockIdx.x * blockDim.x + threadIdx.x;
    if (tid >= BS * NCH) return;
    int b = tid >> 13;
    int c = tid & (NCH - 1);
    int s0 = c << 3;
    BParam p = g_bp[b];

    float pos0 = __fmul_rn((float)s0, POSC);
    int i0s = (int)floorf(pos0);
    i0s = min(i0s, 126);
    int i2x = min(i0s + 2, 127);
    float4 F0a = g_frame[(b * NF + i0s) * 2],     F0b = g_frame[(b * NF + i0s) * 2 + 1];
    float4 F1a = g_frame[(b * NF + i0s + 1) * 2], F1b = g_frame[(b * NF + i0s + 1) * 2 + 1];
    float4 F2a = g_frame[(b * NF + i2x) * 2],     F2b = g_frame[(b * NF + i2x) * 2 + 1];

    float yp1 = 0.f, yp2 = 0.f, u1 = 1.f, u2 = 0.f, v1 = 0.f, v2 = 1.f;
    float dryv[8], envv[8], a1v[8], a2v[8], b0v[8], b1v[8], b2v[8];

    float tt0 = __fdiv_rn((float)s0, SRf);
    bool alive = (tt0 <= p.dur);

    if (alive) {
        float inc = p.inc;
        float i4 = inc * 4.0f, i2 = inc * 2.0f;
        float baseA = (s0 == 0) ? 0.0f : cum_base3(inc, (unsigned)s0);
        float baseB = cum_base3(inc, (unsigned)(s0 + 8));
#pragma unroll
        for (int j = 0; j < 8; j++) {
            int i = s0 + j;
            unsigned l = (unsigned)(j + 1);
            float cum = (l < 8u) ? baseA : baseB;
            if (l & 4u)  cum = __fadd_rn(cum, i4);
            if (l & 2u)  cum = __fadd_rn(cum, i2);
            if (l & 1u)  cum = __fadd_rn(cum, inc);
            float arg = __fadd_rn(__fmul_rn(6.28318548202514648f, cum), p.phase);
            float s = xla_sin(arg);
            float cc = xla_cos(__fmul_rn(arg, 0.5f));
            float sq = xla_tanh(__fmul_rn(__fmul_rn(p.kk, s), 0.5f));
            float vco = __fmul_rn(__fmul_rn(p.sm, sq),
                                  __fadd_rn(1.0f, __fmul_rn(p.shp, cc)));

            float tt = __fdiv_rn((float)i, SRf);
            float ramp = __fsub_rn(1.0f, __fdiv_rn(tt, p.dur));
            ramp = fminf(fmaxf(ramp, 0.001f), 1.0f);
            float env = __powf(ramp, p.alpha);
            if (!(tt <= p.dur)) env = 0.0f;
            envv[j] = env;
            dryv[j] = __fmul_rn(__fmul_rn(vco, p.gain), env);

            float pos = __fmul_rn((float)i, POSC);
            int i0 = min((int)floorf(pos), 126);
            float frc = __fsub_rn(pos, (float)i0);
            float w0 = __fsub_rn(1.0f, frc);
            bool hi = (i0 != i0s);
            float4 fA = hi ? F1a : F0a;
            float4 fB = hi ? F1b : F0b;
            float4 gA = hi ? F2a : F1a;
            float4 gB = hi ? F2b : F1b;
            float a1 = __fadd_rn(__fmul_rn(fA.x, w0), __fmul_rn(gA.x, frc));
            float a2 = __fadd_rn(__fmul_rn(fA.y, w0), __fmul_rn(gA.y, frc));
            a1v[j] = a1; a2v[j] = a2;
            b0v[j] = __fadd_rn(__fmul_rn(fA.z, w0), __fmul_rn(gA.z, frc));
            b1v[j] = __fadd_rn(__fmul_rn(fA.w, w0), __fmul_rn(gA.w, frc));
            b2v[j] = __fadd_rn(__fmul_rn(fB.x, w0), __fmul_rn(gB.x, frc));

            float dj = dryv[j];
            float yp = fmaf(-a1, yp1, fmaf(-a2, yp2, dj));
            float uu = fmaf(-a1, u1, -(a2 * u2));
            float vv = fmaf(-a1, v1, -(a2 * v2));
            yp2 = yp1; yp1 = yp;
            u2 = u1; u1 = uu;
            v2 = v1; v1 = vv;
        }
    } else {
#pragma unroll
        for (int j = 0; j < 8; j++) {
            int i = s0 + j;
            envv[j] = 0.0f;
            dryv[j] = 0.0f;
            float pos = __fmul_rn((float)i, POSC);
            int i0 = min((int)floorf(pos), 126);
            float frc = __fsub_rn(pos, (float)i0);
            float w0 = __fsub_rn(1.0f, frc);
            bool hi = (i0 != i0s);
            float4 fA = hi ? F1a : F0a;
            float4 fB = hi ? F1b : F0b;
            float4 gA = hi ? F2a : F1a;
            float4 gB = hi ? F2b : F1b;
            float a1 = __fadd_rn(__fmul_rn(fA.x, w0), __fmul_rn(gA.x, frc));
            float a2 = __fadd_rn(__fmul_rn(fA.y, w0), __fmul_rn(gA.y, frc));
            a1v[j] = a1; a2v[j] = a2;
            b0v[j] = __fadd_rn(__fmul_rn(fA.z, w0), __fmul_rn(gA.z, frc));
            b1v[j] = __fadd_rn(__fmul_rn(fA.w, w0), __fmul_rn(gA.w, frc));
            b2v[j] = __fadd_rn(__fmul_rn(fB.x, w0), __fmul_rn(gB.x, frc));

            float yp = fmaf(-a1, yp1, fmaf(-a2, yp2, 0.0f));
            float uu = fmaf(-a1, u1, -(a2 * u2));
            float vv = fmaf(-a1, v1, -(a2 * v2));
            yp2 = yp1; yp1 = yp;
            u2 = u1; u1 = uu;
            v2 = v1; v1 = vv;
        }
    }

    size_t base = (size_t)b * NS + s0;
    float4* dptr = (float4*)(out + base);
    dptr[0] = make_float4(dryv[0], dryv[1], dryv[2], dryv[3]);
    dptr[1] = make_float4(dryv[4], dryv[5], dryv[6], dryv[7]);
    float4* eptr = (float4*)(out + 2ull * BS * NS + base);
    eptr[0] = make_float4(envv[0], envv[1], envv[2], envv[3]);
    eptr[1] = make_float4(envv[4], envv[5], envv[6], envv[7]);
    float4* aptr = (float4*)(out + 4ull * BS * NS + base * 3);
    aptr[0] = make_float4(1.0f, a1v[0], a2v[0], 1.0f);
    aptr[1] = make_float4(a1v[1], a2v[1], 1.0f, a1v[2]);
    aptr[2] = make_float4(a2v[2], 1.0f, a1v[3], a2v[3]);
    aptr[3] = make_float4(1.0f, a1v[4], a2v[4], 1.0f);
    aptr[4] = make_float4(a1v[5], a2v[5], 1.0f, a1v[6]);
    aptr[5] = make_float4(a2v[6], 1.0f, a1v[7], a2v[7]);
    float4* bptr = (float4*)(out + 7ull * BS * NS + base * 3);
    bptr[0] = make_float4(b0v[0], b1v[0], b2v[0], b0v[1]);
    bptr[1] = make_float4(b1v[1], b2v[1], b0v[2], b1v[2]);
    bptr[2] = make_float4(b2v[2], b0v[3], b1v[3], b2v[3]);
    bptr[3] = make_float4(b0v[4], b1v[4], b2v[4], b0v[5]);
    bptr[4] = make_float4(b1v[5], b2v[5], b0v[6], b1v[6]);
    bptr[5] = make_float4(b2v[6], b0v[7], b1v[7], b2v[7]);

    float* o = g_chunk + (size_t)tid * 6;
    o[0] = u1; o[1] = v1; o[2] = u2; o[3] = v2; o[4] = yp1; o[5] = yp2;
}

// ---------------- K2: per-voice affine scan (dynamic smem staged) ----------------
__global__ void k_scan2() {
    extern __shared__ float sm[];      // NCH*7 floats, stride-7 records
    int b = blockIdx.x;
    const float* raw = g_chunk + (size_t)b * NCH * 6;
    const int G = NCH / 32;            // 256 chunks per lane
    for (int idx = threadIdx.x; idx < NCH * 6; idx += blockDim.x) {
        int chunk = idx / 6;
        int f = idx - chunk * 6;
        int lane = chunk / G;
        int cpos = chunk - lane * G;
        sm[(cpos * 32 + lane) * 7 + f] = raw[idx];
    }
    __syncthreads();
    if (threadIdx.x < 32) {
        int lane = threadIdx.x;

        float m00 = 1.f, m01 = 0.f, m10 = 0.f, m11 = 1.f, p0 = 0.f, p1 = 0.f;
#pragma unroll 1
        for (int c = 0; c < G; c++) {
            const float* rec = &sm[(c * 32 + lane) * 7];
            float c00 = rec[0], c01 = rec[1], c10 = rec[2], c11 = rec[3], r0 = rec[4], r1 = rec[5];
            float n00 = __fmaf_rn(c00, m00, __fmul_rn(c01, m10));
            float n01 = __fmaf_rn(c00, m01, __fmul_rn(c01, m11));
            float n10 = __fmaf_rn(c10, m00, __fmul_rn(c11, m10));
            float n11 = __fmaf_rn(c10, m01, __fmul_rn(c11, m11));
            float np0 = __fadd_rn(__fmaf_rn(c00, p0, __fmul_rn(c01, p1)), r0);
            float np1 = __fadd_rn(__fmaf_rn(c10, p0, __fmul_rn(c11, p1)), r1);
            m00 = n00; m01 = n01; m10 = n10; m11 = n11; p0 = np0; p1 = np1;
        }
#pragma unroll
        for (int d = 1; d < 32; d <<= 1) {
            float e00 = __shfl_up_sync(0xffffffffu, m00, d);
            float e01 = __shfl_up_sync(0xffffffffu, m01, d);
            float e10 = __shfl_up_sync(0xffffffffu, m10, d);
            float e11 = __shfl_up_sync(0xffffffffu, m11, d);
            float ep0 = __shfl_up_sync(0xffffffffu, p0, d);
            float ep1 = __shfl_up_sync(0xffffffffu, p1, d);
            if (lane >= d) {
                float n00 = __fmaf_rn(m00, e00, __fmul_rn(m01, e10));
                float n01 = __fmaf_rn(m00, e01, __fmul_rn(m01, e11));
                float n10 = __fmaf_rn(m10, e00, __fmul_rn(m11, e10));
                float n11 = __fmaf_rn(m10, e01, __fmul_rn(m11, e11));
                float np0 = __fadd_rn(__fmaf_rn(m00, ep0, __fmul_rn(m01, ep1)), p0);
                float np1 = __fadd_rn(__fmaf_rn(m10, ep0, __fmul_rn(m11, ep1)), p1);
                m00 = n00; m01 = n01; m10 = n10; m11 = n11; p0 = np0; p1 = np1;
            }
        }
        float s0 = __shfl_up_sync(0xffffffffu, p0, 1);
        float s1 = __shfl_up_sync(0xffffffffu, p1, 1);
        if (lane == 0) { s0 = 0.f; s1 = 0.f; }

#pragma unroll 1
        for (int c = 0; c < G; c++) {
            g_init[(size_t)b * NCH + lane * G + c] = make_float2(s0, s1);
            const float* rec = &sm[(c * 32 + lane) * 7];
            float c00 = rec[0], c01 = rec[1], c10 = rec[2], c11 = rec[3], r0 = rec[4], r1 = rec[5];
            float ns0 = __fadd_rn(__fmaf_rn(c00, s0, __fmul_rn(c01, s1)), r0);
            float ns1 = __fadd_rn(__fmaf_rn(c10, s0, __fmul_rn(c11, s1)), r1);
            s0 = ns0; s1 = ns1;
        }
    }
}

// ---------------- K3: pass 2 — coeff recompute + IIR + FIR + tanh (R8 structure) ----------------
__global__ void k_pass2(float* __restrict__ out) {
    int tid = blockIdx.x * blockDim.x + threadIdx.x;
    if (tid >= BS * NCH) return;
    int b = tid >> 13;
    int c = tid & (NCH - 1);
    int s0 = c << 3;
    size_t base = (size_t)b * NS + s0;
    const float* dry = out + base;
    float* w_wet = out + 1ull * BS * NS + base;
    float* w_yab = out + 3ull * BS * NS + base;
    float* w_ya = out + 10ull * BS * NS + base;

    float pos0 = __fmul_rn((float)s0, POSC);
    int i0s = (int)floorf(pos0);
    i0s = min(i0s, 126);
    int i2x = min(i0s + 2, 127);
    float4 F0a = g_frame[(b * NF + i0s) * 2],     F0b = g_frame[(b * NF + i0s) * 2 + 1];
    float4 F1a = g_frame[(b * NF + i0s + 1) * 2], F1b = g_frame[(b * NF + i0s + 1) * 2 + 1];
    float4 F2a = g_frame[(b * NF + i2x) * 2],     F2b = g_frame[(b * NF + i2x) * 2 + 1];

    float2 ini = g_init[tid];
    float y1 = ini.x, y2 = ini.y;
    float dg = g_bp[b].dist;

    float4 x0 = *(const float4*)(dry);
    float4 x1 = *(const float4*)(dry + 4);
    float xs[8] = {x0.x, x0.y, x0.z, x0.w, x1.x, x1.y, x1.z, x1.w};
    float ya[8], yb[8], wt[8];
#pragma unroll
    for (int j = 0; j < 8; j++) {
        int i = s0 + j;
        float pos = __fmul_rn((float)i, POSC);
        int i0 = min((int)floorf(pos), 126);
        float frc = __fsub_rn(pos, (float)i0);
        float w0 = __fsub_rn(1.0f, frc);
        bool hi = (i0 != i0s);
        float4 fA = hi ? F1a : F0a;
        float4 fB = hi ? F1b : F0b;
        float4 gA = hi ? F2a : F1a;
        float4 gB = hi ? F2b : F1b;
        float a1 = __fadd_rn(__fmul_rn(fA.x, w0), __fmul_rn(gA.x, frc));
        float a2 = __fadd_rn(__fmul_rn(fA.y, w0), __fmul_rn(gA.y, frc));
        float c0 = __fadd_rn(__fmul_rn(fA.z, w0), __fmul_rn(gA.z, frc));
        float c1 = __fadd_rn(__fmul_rn(fA.w, w0), __fmul_rn(gA.w, frc));
        float c2 = __fadd_rn(__fmul_rn(fB.x, w0), __fmul_rn(gB.x, frc));

        float y = __fsub_rn(__fsub_rn(xs[j], __fmul_rn(a1, y1)), __fmul_rn(a2, y2));
        float v = __fadd_rn(__fadd_rn(__fmul_rn(c0, y), __fmul_rn(c1, y1)),
                            __fmul_rn(c2, y2));
        ya[j] = y; yb[j] = v;
        wt[j] = xla_tanh(__fmul_rn(v, dg));
        y2 = y1; y1 = y;
    }
    ((float4*)w_ya)[0] = make_float4(ya[0], ya[1], ya[2], ya[3]);
    ((float4*)w_ya)[1] = make_float4(ya[4], ya[5], ya[6], ya[7]);
    ((float4*)w_yab)[0] = make_float4(yb[0], yb[1], yb[2], yb[3]);
    ((float4*)w_yab)[1] = make_float4(yb[4], yb[5], yb[6], yb[7]);
    ((float4*)w_wet)[0] = make_float4(wt[0], wt[1], wt[2], wt[3]);
    ((float4*)w_wet)[1] = make_float4(wt[4], wt[5], wt[6], wt[7]);
}

extern "C" void kernel_launch(void* const* d_in, const int* in_sizes, int n_in,
                              void* d_out, int out_size) {
    const float* f0_hz = (const float*)d_in[0];
    const float* note_on = (const float*)d_in[1];
    const float* phase = (const float*)d_in[2];
    const float* logits = (const float*)d_in[3];
    const float* osc_shape = (const float*)d_in[4];
    const float* osc_gain = (const float*)d_in[5];
    const float* dist_gain = (const float*)d_in[6];
    const float* learned_alpha = (const float*)d_in[7];
    float* out = (float*)d_out;

    static int smem_set = 0;
    const int scan_smem = NCH * 7 * sizeof(float);   // 229376 B
    if (!smem_set) {
        cudaFuncSetAttribute(k_scan2, cudaFuncAttributeMaxDynamicSharedMemorySize, scan_smem);
        smem_set = 1;
    }

    k_prep<<<(BS * NF + 255) / 256, 256>>>(f0_hz, note_on, phase, logits,
                                           osc_shape, osc_gain, dist_gain, learned_alpha);
    k_mainp1<<<(BS * NCH + 127) / 128, 128>>>(out);
    k_scan2<<<BS, 1024, scan_smem>>>();
    k_pass2<<<(BS * NCH + 127) / 128, 128>>>(out);
}

// round 11
// speedup vs baseline: 1.0655x; 1.0071x over previous
#include <cuda_runtime.h>
#include <math.h>
#include <stdint.h>

#define BS 32
#define NS 65536
#define NF 128
#define CHUNK 8
#define NCH (NS / CHUNK)      // 8192
#define SRf 48000.0f
#define STAB 0.999f
#define POSC (127.0f / 65535.0f)
#define R48 (1.0f / 48000.0f)   // compile-time correctly-rounded reciprocal

// Output plane offsets (elements of BS*NS):
// dry=0, wet=1, env=2, y_ab=3, a_coeff3=4..6, b_coeff=7..9, y_a=10

struct BParam {
    float inc, phase, kk, shp;
    float sm, gain, dur, alpha;
    float dist, rdur, pad1, pad2;
};

__device__ BParam g_bp[BS];
__device__ float4 g_frame[BS * NF * 2];   // per frame: {a1,a2,b0,b1},{b2,-,-,-}
__device__ float  g_chunk[BS * NCH * 6];  // u1,v1,u2,v2,yp1,yp2
__device__ float2 g_init[BS * NCH];

// Markstein correctly-rounded division by constant d given r = fl(1/d).
__device__ __forceinline__ float div_cr(float x, float d, float r) {
    float q0 = __fmul_rn(x, r);
    float rem = fmaf(-q0, d, x);
    return fmaf(rem, r, q0);
}

// ---- XLA rational tanh (Eigen fast tanh) ----
__device__ __forceinline__ float xla_tanh(float x) {
    const float kClamp = 7.90531110763549805f;
    float xc = fminf(fmaxf(x, -kClamp), kClamp);
    float x2 = __fmul_rn(xc, xc);
    float p = __fadd_rn(2.00018790482477e-13f, __fmul_rn(x2, -2.76076847742355e-16f));
    p = __fadd_rn(-8.60467152213735e-11f, __fmul_rn(x2, p));
    p = __fadd_rn(5.12229709037114e-08f,  __fmul_rn(x2, p));
    p = __fadd_rn(1.48572235717979e-05f,  __fmul_rn(x2, p));
    p = __fadd_rn(6.37261928875436e-04f,  __fmul_rn(x2, p));
    p = __fadd_rn(4.89352455891786e-03f,  __fmul_rn(x2, p));
    float num = __fmul_rn(xc, p);
    float q = __fadd_rn(1.18534705686654e-04f, __fmul_rn(x2, 1.19825839466702e-06f));
    q = __fadd_rn(2.26843463243900e-03f, __fmul_rn(x2, q));
    q = __fadd_rn(4.89352518554385e-03f, __fmul_rn(x2, q));
    float r = __fdiv_rn(num, q);
    return (fabsf(x) < 0.0004f) ? x : r;
}

// ---- fast minimax sin/cos kernel for |r| <= ~pi (post 2pi-reduction) ----
__device__ __forceinline__ void fast_sc(float r, float& ps, float& pc, int& iq) {
    float qf = rintf(r * 0.636619772367581343f);
    float t = fmaf(qf, -1.57079637050628662109f, r);
    t = fmaf(qf, 4.37113900018624283e-8f, t);
    iq = ((int)qf) & 3;
    float t2 = t * t;
    float s = fmaf(t2, 2.7557314297e-06f, -1.9841270114e-04f);
    s = fmaf(t2, s, 8.3333337680e-03f);
    s = fmaf(t2, s, -1.6666667163e-01f);
    ps = fmaf(t * t2, s, t);
    float c = fmaf(t2, 2.4801587642e-05f, -1.3888889225e-03f);
    c = fmaf(t2, c, 4.1666667908e-02f);
    c = fmaf(t2, c, -0.5f);
    pc = fmaf(t2, c, 1.0f);
}
__device__ __forceinline__ float fast_sin(float r) {
    float ps, pc; int iq;
    fast_sc(r, ps, pc, iq);
    float v = (iq & 1) ? pc : ps;
    return (iq & 2) ? -v : v;
}
__device__ __forceinline__ float fast_cos(float r) {
    float ps, pc; int iq;
    fast_sc(r, ps, pc, iq);
    float v = (iq & 1) ? ps : pc;
    return ((iq + 1) & 2) ? -v : v;
}
__device__ __forceinline__ float xla_sin(float x) {
    float k = rintf(__fmul_rn(x, 0.15915494309189535f));
    float r = fmaf(-k, 6.28318548202514648f, x);
    return fast_sin(r);
}

// Chain over bits >=3 of v (v multiple of 8, v>0): MSB->LSB rounded adds.
__device__ __forceinline__ float cum_base3(float c, unsigned v) {
    int msb = 31 - __clz(v);
    float r = c * __int_as_float((127 + msb) << 23);
#pragma unroll 1
    for (int k = msb - 1; k >= 3; k--) {
        if ((v >> k) & 1u)
            r = __fadd_rn(r, c * __int_as_float((127 + k) << 23));
    }
    return r;
}

// ---------------- K0 ----------------
__global__ void k_prep(const float* __restrict__ f0_hz,
                       const float* __restrict__ durp,
                       const float* __restrict__ phasep,
                       const float* __restrict__ logits,
                       const float* __restrict__ shpp,
                       const float* __restrict__ gainp,
                       const float* __restrict__ distp,
                       const float* __restrict__ alphap) {
    int tid = blockIdx.x * blockDim.x + threadIdx.x;
    if (tid >= BS * NF) return;
    int b = tid / NF;
    int f = tid - b * NF;
    const float* lg = logits + (size_t)tid * 5;
    float th0 = xla_tanh(lg[0]);
    float a1 = __fmul_rn(__fmul_rn(2.0f, th0), STAB);
    float a1a = fabsf(a1);
    float th1 = xla_tanh(lg[1]);
    float a2 = __fdiv_rn(__fadd_rn(__fmul_rn(__fmul_rn(__fsub_rn(2.0f, a1a), th1), STAB), a1a), 2.0f);
    g_frame[tid * 2]     = make_float4(a1, a2, lg[2], lg[3]);
    g_frame[tid * 2 + 1] = make_float4(lg[4], 0.f, 0.f, 0.f);
    if (f == 0) {
        BParam p;
        float f0 = f0_hz[b];
        p.inc = __fdiv_rn(f0, SRf);
        p.phase = phasep[b];
        float partials = __fdiv_rn(12000.0f, __fmul_rn(f0, log10f(f0)));
        p.kk = __fmul_rn(3.14159274101257324f, partials);
        p.shp = shpp[b];
        p.sm = __fsub_rn(1.0f, __fmul_rn(shpp[b], 0.5f));
        p.gain = gainp[b];
        p.dur = durp[b];
        p.alpha = alphap[b];
        p.dist = distp[b];
        p.rdur = __fdiv_rn(1.0f, durp[b]);   // correctly-rounded reciprocal
        g_bp[b] = p;
    }
}

// ---------------- K1: osc + env + coeff interp + fused pass1 ----------------
__global__ void k_mainp1(float* __restrict__ out) {
    int tid = blockIdx.x * blockDim.x + threadIdx.x;
    if (tid >= BS * NCH) return;
    int b = tid >> 13;
    int c = tid & (NCH - 1);
    int s0 = c << 3;
    BParam p = g_bp[b];

    float pos0 = __fmul_rn((float)s0, POSC);
    int i0s = (int)floorf(pos0);
    i0s = min(i0s, 126);
    int i2x = min(i0s + 2, 127);
    float4 F0a = g_frame[(b * NF + i0s) * 2],     F0b = g_frame[(b * NF + i0s) * 2 + 1];
    float4 F1a = g_frame[(b * NF + i0s + 1) * 2], F1b = g_frame[(b * NF + i0s + 1) * 2 + 1];
    float4 F2a = g_frame[(b * NF + i2x) * 2],     F2b = g_frame[(b * NF + i2x) * 2 + 1];

    float yp1 = 0.f, yp2 = 0.f, u1 = 1.f, u2 = 0.f, v1 = 0.f, v2 = 1.f;
    float dryv[8], envv[8], a1v[8], a2v[8], b0v[8], b1v[8], b2v[8];

    float tt0 = div_cr((float)s0, SRf, R48);
    bool alive = (tt0 <= p.dur);

    if (alive) {
        float inc = p.inc;
        float i4 = inc * 4.0f, i2 = inc * 2.0f;
        float baseA = (s0 == 0) ? 0.0f : cum_base3(inc, (unsigned)s0);
        float baseB = cum_base3(inc, (unsigned)(s0 + 8));
#pragma unroll
        for (int j = 0; j < 8; j++) {
            int i = s0 + j;
            unsigned l = (unsigned)(j + 1);
            float cum = (l < 8u) ? baseA : baseB;
            if (l & 4u)  cum = __fadd_rn(cum, i4);
            if (l & 2u)  cum = __fadd_rn(cum, i2);
            if (l & 1u)  cum = __fadd_rn(cum, inc);
            float arg = __fadd_rn(__fmul_rn(6.28318548202514648f, cum), p.phase);
            float carg = __fmul_rn(arg, 0.5f);
            // single reduction + single fast_sc: cos(carg) direct,
            // sin(arg) = 2 sin(carg) cos(carg)
            float kq = rintf(__fmul_rn(carg, 0.15915494309189535f));
            float rr = fmaf(-kq, 6.28318548202514648f, carg);
            float ps, pc; int iq;
            fast_sc(rr, ps, pc, iq);
            float sh = (iq & 1) ? pc : ps; sh = (iq & 2) ? -sh : sh;
            float ch = (iq & 1) ? ps : pc; ch = ((iq + 1) & 2) ? -ch : ch;
            float cc = ch;
            float s = 2.0f * sh * ch;

            float sq = xla_tanh(__fmul_rn(__fmul_rn(p.kk, s), 0.5f));
            float vco = __fmul_rn(__fmul_rn(p.sm, sq),
                                  __fadd_rn(1.0f, __fmul_rn(p.shp, cc)));

            float tt = div_cr((float)i, SRf, R48);
            float ramp = __fsub_rn(1.0f, div_cr(tt, p.dur, p.rdur));
            ramp = fminf(fmaxf(ramp, 0.001f), 1.0f);
            float env = __powf(ramp, p.alpha);
            if (!(tt <= p.dur)) env = 0.0f;
            envv[j] = env;
            dryv[j] = __fmul_rn(__fmul_rn(vco, p.gain), env);

            float pos = __fmul_rn((float)i, POSC);
            int i0 = min((int)floorf(pos), 126);
            float frc = __fsub_rn(pos, (float)i0);
            float w0 = __fsub_rn(1.0f, frc);
            bool hi = (i0 != i0s);
            float4 fA = hi ? F1a : F0a;
            float4 fB = hi ? F1b : F0b;
            float4 gA = hi ? F2a : F1a;
            float4 gB = hi ? F2b : F1b;
            float a1 = __fadd_rn(__fmul_rn(fA.x, w0), __fmul_rn(gA.x, frc));
            float a2 = __fadd_rn(__fmul_rn(fA.y, w0), __fmul_rn(gA.y, frc));
            a1v[j] = a1; a2v[j] = a2;
            b0v[j] = __fadd_rn(__fmul_rn(fA.z, w0), __fmul_rn(gA.z, frc));
            b1v[j] = __fadd_rn(__fmul_rn(fA.w, w0), __fmul_rn(gA.w, frc));
            b2v[j] = __fadd_rn(__fmul_rn(fB.x, w0), __fmul_rn(gB.x, frc));

            float dj = dryv[j];
            float yp = fmaf(-a1, yp1, fmaf(-a2, yp2, dj));
            float uu = fmaf(-a1, u1, -(a2 * u2));
            float vv = fmaf(-a1, v1, -(a2 * v2));
            yp2 = yp1; yp1 = yp;
            u2 = u1; u1 = uu;
            v2 = v1; v1 = vv;
        }
    } else {
        // dead chunk: x=0 and zero-init particular response stays exactly 0
#pragma unroll
        for (int j = 0; j < 8; j++) {
            int i = s0 + j;
            envv[j] = 0.0f;
            dryv[j] = 0.0f;
            float pos = __fmul_rn((float)i, POSC);
            int i0 = min((int)floorf(pos), 126);
            float frc = __fsub_rn(pos, (float)i0);
            float w0 = __fsub_rn(1.0f, frc);
            bool hi = (i0 != i0s);
            float4 fA = hi ? F1a : F0a;
            float4 fB = hi ? F1b : F0b;
            float4 gA = hi ? F2a : F1a;
            float4 gB = hi ? F2b : F1b;
            float a1 = __fadd_rn(__fmul_rn(fA.x, w0), __fmul_rn(gA.x, frc));
            float a2 = __fadd_rn(__fmul_rn(fA.y, w0), __fmul_rn(gA.y, frc));
            a1v[j] = a1; a2v[j] = a2;
            b0v[j] = __fadd_rn(__fmul_rn(fA.z, w0), __fmul_rn(gA.z, frc));
            b1v[j] = __fadd_rn(__fmul_rn(fA.w, w0), __fmul_rn(gA.w, frc));
            b2v[j] = __fadd_rn(__fmul_rn(fB.x, w0), __fmul_rn(gB.x, frc));

            float uu = fmaf(-a1, u1, -(a2 * u2));
            float vv = fmaf(-a1, v1, -(a2 * v2));
            u2 = u1; u1 = uu;
            v2 = v1; v1 = vv;
        }
        yp1 = 0.f; yp2 = 0.f;
    }

    size_t base = (size_t)b * NS + s0;
    float4* dptr = (float4*)(out + base);
    dptr[0] = make_float4(dryv[0], dryv[1], dryv[2], dryv[3]);
    dptr[1] = make_float4(dryv[4], dryv[5], dryv[6], dryv[7]);
    float4* eptr = (float4*)(out + 2ull * BS * NS + base);
    eptr[0] = make_float4(envv[0], envv[1], envv[2], envv[3]);
    eptr[1] = make_float4(envv[4], envv[5], envv[6], envv[7]);
    float4* aptr = (float4*)(out + 4ull * BS * NS + base * 3);
    aptr[0] = make_float4(1.0f, a1v[0], a2v[0], 1.0f);
    aptr[1] = make_float4(a1v[1], a2v[1], 1.0f, a1v[2]);
    aptr[2] = make_float4(a2v[2], 1.0f, a1v[3], a2v[3]);
    aptr[3] = make_float4(1.0f, a1v[4], a2v[4], 1.0f);
    aptr[4] = make_float4(a1v[5], a2v[5], 1.0f, a1v[6]);
    aptr[5] = make_float4(a2v[6], 1.0f, a1v[7], a2v[7]);
    float4* bptr = (float4*)(out + 7ull * BS * NS + base * 3);
    bptr[0] = make_float4(b0v[0], b1v[0], b2v[0], b0v[1]);
    bptr[1] = make_float4(b1v[1], b2v[1], b0v[2], b1v[2]);
    bptr[2] = make_float4(b2v[2], b0v[3], b1v[3], b2v[3]);
    bptr[3] = make_float4(b0v[4], b1v[4], b2v[4], b0v[5]);
    bptr[4] = make_float4(b1v[5], b2v[5], b0v[6], b1v[6]);
    bptr[5] = make_float4(b2v[6], b0v[7], b1v[7], b2v[7]);

    float* o = g_chunk + (size_t)tid * 6;
    o[0] = u1; o[1] = v1; o[2] = u2; o[3] = v2; o[4] = yp1; o[5] = yp2;
}

// ---------------- K2: per-voice affine scan (dynamic smem staged) ----------------
__global__ void k_scan2() {
    extern __shared__ float sm[];      // NCH*7 floats, stride-7 records
    int b = blockIdx.x;
    const float* raw = g_chunk + (size_t)b * NCH * 6;
    const int G = NCH / 32;            // 256 chunks per lane
    for (int idx = threadIdx.x; idx < NCH * 6; idx += blockDim.x) {
        int chunk = idx / 6;
        int f = idx - chunk * 6;
        int lane = chunk / G;
        int cpos = chunk - lane * G;
        sm[(cpos * 32 + lane) * 7 + f] = raw[idx];
    }
    __syncthreads();
    if (threadIdx.x < 32) {
        int lane = threadIdx.x;

        float m00 = 1.f, m01 = 0.f, m10 = 0.f, m11 = 1.f, p0 = 0.f, p1 = 0.f;
#pragma unroll 1
        for (int c = 0; c < G; c++) {
            const float* rec = &sm[(c * 32 + lane) * 7];
            float c00 = rec[0], c01 = rec[1], c10 = rec[2], c11 = rec[3], r0 = rec[4], r1 = rec[5];
            float n00 = __fmaf_rn(c00, m00, __fmul_rn(c01, m10));
            float n01 = __fmaf_rn(c00, m01, __fmul_rn(c01, m11));
            float n10 = __fmaf_rn(c10, m00, __fmul_rn(c11, m10));
            float n11 = __fmaf_rn(c10, m01, __fmul_rn(c11, m11));
            float np0 = __fadd_rn(__fmaf_rn(c00, p0, __fmul_rn(c01, p1)), r0);
            float np1 = __fadd_rn(__fmaf_rn(c10, p0, __fmul_rn(c11, p1)), r1);
            m00 = n00; m01 = n01; m10 = n10; m11 = n11; p0 = np0; p1 = np1;
        }
#pragma unroll
        for (int d = 1; d < 32; d <<= 1) {
            float e00 = __shfl_up_sync(0xffffffffu, m00, d);
            float e01 = __shfl_up_sync(0xffffffffu, m01, d);
            float e10 = __shfl_up_sync(0xffffffffu, m10, d);
            float e11 = __shfl_up_sync(0xffffffffu, m11, d);
            float ep0 = __shfl_up_sync(0xffffffffu, p0, d);
            float ep1 = __shfl_up_sync(0xffffffffu, p1, d);
            if (lane >= d) {
                float n00 = __fmaf_rn(m00, e00, __fmul_rn(m01, e10));
                float n01 = __fmaf_rn(m00, e01, __fmul_rn(m01, e11));
                float n10 = __fmaf_rn(m10, e00, __fmul_rn(m11, e10));
                float n11 = __fmaf_rn(m10, e01, __fmul_rn(m11, e11));
                float np0 = __fadd_rn(__fmaf_rn(m00, ep0, __fmul_rn(m01, ep1)), p0);
                float np1 = __fadd_rn(__fmaf_rn(m10, ep0, __fmul_rn(m11, ep1)), p1);
                m00 = n00; m01 = n01; m10 = n10; m11 = n11; p0 = np0; p1 = np1;
            }
        }
        float s0 = __shfl_up_sync(0xffffffffu, p0, 1);
        float s1 = __shfl_up_sync(0xffffffffu, p1, 1);
        if (lane == 0) { s0 = 0.f; s1 = 0.f; }

#pragma unroll 1
        for (int c = 0; c < G; c++) {
            g_init[(size_t)b * NCH + lane * G + c] = make_float2(s0, s1);
            const float* rec = &sm[(c * 32 + lane) * 7];
            float c00 = rec[0], c01 = rec[1], c10 = rec[2], c11 = rec[3], r0 = rec[4], r1 = rec[5];
            float ns0 = __fadd_rn(__fmaf_rn(c00, s0, __fmul_rn(c01, s1)), r0);
            float ns1 = __fadd_rn(__fmaf_rn(c10, s0, __fmul_rn(c11, s1)), r1);
            s0 = ns0; s1 = ns1;
        }
    }
}

// ---------------- K3: pass 2 — coeff recompute + IIR + FIR + tanh ----------------
__global__ void k_pass2(float* __restrict__ out) {
    int tid = blockIdx.x * blockDim.x + threadIdx.x;
    if (tid >= BS * NCH) return;
    int b = tid >> 13;
    int c = tid & (NCH - 1);
    int s0 = c << 3;
    size_t base = (size_t)b * NS + s0;
    const float* dry = out + base;
    float* w_wet = out + 1ull * BS * NS + base;
    float* w_yab = out + 3ull * BS * NS + base;
    float* w_ya = out + 10ull * BS * NS + base;

    float pos0 = __fmul_rn((float)s0, POSC);
    int i0s = (int)floorf(pos0);
    i0s = min(i0s, 126);
    int i2x = min(i0s + 2, 127);
    float4 F0a = g_frame[(b * NF + i0s) * 2],     F0b = g_frame[(b * NF + i0s) * 2 + 1];
    float4 F1a = g_frame[(b * NF + i0s + 1) * 2], F1b = g_frame[(b * NF + i0s + 1) * 2 + 1];
    float4 F2a = g_frame[(b * NF + i2x) * 2],     F2b = g_frame[(b * NF + i2x) * 2 + 1];

    float2 ini = g_init[tid];
    float y1 = ini.x, y2 = ini.y;
    float dg = g_bp[b].dist;

    float4 x0 = *(const float4*)(dry);
    float4 x1 = *(const float4*)(dry + 4);
    float xs[8] = {x0.x, x0.y, x0.z, x0.w, x1.x, x1.y, x1.z, x1.w};
    float ya[8], yb[8], wt[8];
#pragma unroll
    for (int j = 0; j < 8; j++) {
        int i = s0 + j;
        float pos = __fmul_rn((float)i, POSC);
        int i0 = min((int)floorf(pos), 126);
        float frc = __fsub_rn(pos, (float)i0);
        float w0 = __fsub_rn(1.0f, frc);
        bool hi = (i0 != i0s);
        float4 fA = hi ? F1a : F0a;
        float4 fB = hi ? F1b : F0b;
        float4 gA = hi ? F2a : F1a;
        float4 gB = hi ? F2b : F1b;
        float a1 = __fadd_rn(__fmul_rn(fA.x, w0), __fmul_rn(gA.x, frc));
        float a2 = __fadd_rn(__fmul_rn(fA.y, w0), __fmul_rn(gA.y, frc));
        float c0 = __fadd_rn(__fmul_rn(fA.z, w0), __fmul_rn(gA.z, frc));
        float c1 = __fadd_rn(__fmul_rn(fA.w, w0), __fmul_rn(gA.w, frc));
        float c2 = __fadd_rn(__fmul_rn(fB.x, w0), __fmul_rn(gB.x, frc));

        float y = __fsub_rn(__fsub_rn(xs[j], __fmul_rn(a1, y1)), __fmul_rn(a2, y2));
        float v = __fadd_rn(__fadd_rn(__fmul_rn(c0, y), __fmul_rn(c1, y1)),
                            __fmul_rn(c2, y2));
        ya[j] = y; yb[j] = v;
        wt[j] = xla_tanh(__fmul_rn(v, dg));
        y2 = y1; y1 = y;
    }
    ((float4*)w_ya)[0] = make_float4(ya[0], ya[1], ya[2], ya[3]);
    ((float4*)w_ya)[1] = make_float4(ya[4], ya[5], ya[6], ya[7]);
    ((float4*)w_yab)[0] = make_float4(yb[0], yb[1], yb[2], yb[3]);
    ((float4*)w_yab)[1] = make_float4(yb[4], yb[5], yb[6], yb[7]);
    ((float4*)w_wet)[0] = make_float4(wt[0], wt[1], wt[2], wt[3]);
    ((float4*)w_wet)[1] = make_float4(wt[4], wt[5], wt[6], wt[7]);
}

extern "C" void kernel_launch(void* const* d_in, const int* in_sizes, int n_in,
                              void* d_out, int out_size) {
    const float* f0_hz = (const float*)d_in[0];
    const float* note_on = (const float*)d_in[1];
    const float* phase = (const float*)d_in[2];
    const float* logits = (const float*)d_in[3];
    const float* osc_shape = (const float*)d_in[4];
    const float* osc_gain = (const float*)d_in[5];
    const float* dist_gain = (const float*)d_in[6];
    const float* learned_alpha = (const float*)d_in[7];
    float* out = (float*)d_out;

    static int smem_set = 0;
    const int scan_smem = NCH * 7 * sizeof(float);   // 229376 B
    if (!smem_set) {
        cudaFuncSetAttribute(k_scan2, cudaFuncAttributeMaxDynamicSharedMemorySize, scan_smem);
        smem_set = 1;
    }

    k_prep<<<(BS * NF + 255) / 256, 256>>>(f0_hz, note_on, phase, logits,
                                           osc_shape, osc_gain, dist_gain, learned_alpha);
    k_mainp1<<<(BS * NCH + 127) / 128, 128>>>(out);
    k_scan2<<<BS, 1024, scan_smem>>>();
    k_pass2<<<(BS * NCH + 127) / 128, 128>>>(out);
}

// round 13
// speedup vs baseline: 1.2072x; 1.1330x over previous
#include <cuda_runtime.h>
#include <math.h>
#include <stdint.h>

#define BS 32
#define NS 65536
#define NF 128
#define CHUNK 8
#define NCH (NS / CHUNK)      // 8192
#define SRf 48000.0f
#define STAB 0.999f
#define POSC (127.0f / 65535.0f)
#define R48 (1.0f / 48000.0f)

// Output plane offsets (elements of BS*NS):
// dry=0, wet=1, env=2, y_ab=3, a_coeff3=4..6, b_coeff=7..9, y_a=10

__device__ float4 g_frame[BS * NF * 2];   // {a1,a2,b0,b1},{b2,-,-,-} (written by scan for pass2)
__device__ float  g_chunk[BS * NCH * 6];  // u1,v1,u2,v2,yp1,yp2
__device__ float2 g_init[BS * NCH];

// Markstein correctly-rounded division by constant d given r = fl(1/d).
__device__ __forceinline__ float div_cr(float x, float d, float r) {
    float q0 = __fmul_rn(x, r);
    float rem = fmaf(-q0, d, x);
    return fmaf(rem, r, q0);
}

// ---- XLA rational tanh: CR-div version (coeff path, must be bit-stable) ----
__device__ __forceinline__ float xla_tanh_cr(float x) {
    const float kClamp = 7.90531110763549805f;
    float xc = fminf(fmaxf(x, -kClamp), kClamp);
    float x2 = __fmul_rn(xc, xc);
    float p = __fadd_rn(2.00018790482477e-13f, __fmul_rn(x2, -2.76076847742355e-16f));
    p = __fadd_rn(-8.60467152213735e-11f, __fmul_rn(x2, p));
    p = __fadd_rn(5.12229709037114e-08f,  __fmul_rn(x2, p));
    p = __fadd_rn(1.48572235717979e-05f,  __fmul_rn(x2, p));
    p = __fadd_rn(6.37261928875436e-04f,  __fmul_rn(x2, p));
    p = __fadd_rn(4.89352455891786e-03f,  __fmul_rn(x2, p));
    float num = __fmul_rn(xc, p);
    float q = __fadd_rn(1.18534705686654e-04f, __fmul_rn(x2, 1.19825839466702e-06f));
    q = __fadd_rn(2.26843463243900e-03f, __fmul_rn(x2, q));
    q = __fadd_rn(4.89352518554385e-03f, __fmul_rn(x2, q));
    float r = __fdiv_rn(num, q);
    return (fabsf(x) < 0.0004f) ? x : r;
}

// ---- fast-div version (per-sample path; ~2ulp) ----
__device__ __forceinline__ float xla_tanh_f(float x) {
    const float kClamp = 7.90531110763549805f;
    float xc = fminf(fmaxf(x, -kClamp), kClamp);
    float x2 = __fmul_rn(xc, xc);
    float p = __fadd_rn(2.00018790482477e-13f, __fmul_rn(x2, -2.76076847742355e-16f));
    p = __fadd_rn(-8.60467152213735e-11f, __fmul_rn(x2, p));
    p = __fadd_rn(5.12229709037114e-08f,  __fmul_rn(x2, p));
    p = __fadd_rn(1.48572235717979e-05f,  __fmul_rn(x2, p));
    p = __fadd_rn(6.37261928875436e-04f,  __fmul_rn(x2, p));
    p = __fadd_rn(4.89352455891786e-03f,  __fmul_rn(x2, p));
    float num = __fmul_rn(xc, p);
    float q = __fadd_rn(1.18534705686654e-04f, __fmul_rn(x2, 1.19825839466702e-06f));
    q = __fadd_rn(2.26843463243900e-03f, __fmul_rn(x2, q));
    q = __fadd_rn(4.89352518554385e-03f, __fmul_rn(x2, q));
    float r = __fdividef(num, q);
    return (fabsf(x) < 0.0004f) ? x : r;
}

// ---- fast minimax sin/cos kernel for |r| <= ~pi ----
__device__ __forceinline__ void fast_sc(float r, float& ps, float& pc, int& iq) {
    float qf = rintf(r * 0.636619772367581343f);
    float t = fmaf(qf, -1.57079637050628662109f, r);
    t = fmaf(qf, 4.37113900018624283e-8f, t);
    iq = ((int)qf) & 3;
    float t2 = t * t;
    float s = fmaf(t2, 2.7557314297e-06f, -1.9841270114e-04f);
    s = fmaf(t2, s, 8.3333337680e-03f);
    s = fmaf(t2, s, -1.6666667163e-01f);
    ps = fmaf(t * t2, s, t);
    float c = fmaf(t2, 2.4801587642e-05f, -1.3888889225e-03f);
    c = fmaf(t2, c, 4.1666667908e-02f);
    c = fmaf(t2, c, -0.5f);
    pc = fmaf(t2, c, 1.0f);
}

// Chain over bits >=3 of v (v multiple of 8, v>0).
__device__ __forceinline__ float cum_base3(float c, unsigned v) {
    int msb = 31 - __clz(v);
    float r = c * __int_as_float((127 + msb) << 23);
#pragma unroll 1
    for (int k = msb - 1; k >= 3; k--) {
        if ((v >> k) & 1u)
            r = __fadd_rn(r, c * __int_as_float((127 + k) << 23));
    }
    return r;
}

// frame coeffs from logits (identical to old k_prep)
__device__ __forceinline__ void compute_frame(const float* __restrict__ lg, float* dst) {
    float th0 = xla_tanh_cr(lg[0]);
    float a1 = __fmul_rn(__fmul_rn(2.0f, th0), STAB);
    float a1a = fabsf(a1);
    float th1 = xla_tanh_cr(lg[1]);
    float a2 = __fdiv_rn(__fadd_rn(__fmul_rn(__fmul_rn(__fsub_rn(2.0f, a1a), th1), STAB), a1a), 2.0f);
    dst[0] = a1; dst[1] = a2; dst[2] = lg[2]; dst[3] = lg[3]; dst[4] = lg[4];
}

// ---------------- K1: osc + env + coeff interp + fused pass1 (self-contained) ----------------
__global__ void k_mainp1(float* __restrict__ out,
                         const float* __restrict__ f0_hz,
                         const float* __restrict__ durp,
                         const float* __restrict__ phasep,
                         const float* __restrict__ logits,
                         const float* __restrict__ shpp,
                         const float* __restrict__ gainp,
                         const float* __restrict__ alphap) {
    __shared__ float sfr[5][5];      // frames f_first .. f_first+4: {a1,a2,b0,b1,b2}
    __shared__ float sbp[12];        // inc,phase,kk,shp,sm,gain,dur,alpha,rdur

    int tid = blockIdx.x * blockDim.x + threadIdx.x;
    int b = tid >> 13;
    int c = tid & (NCH - 1);
    int s0 = c << 3;

    int BS0 = (blockIdx.x & 63) << 10;   // block's first sample within voice
    float bpos0 = __fmul_rn((float)BS0, POSC);
    int f_first = min((int)floorf(bpos0), 126);

    if (threadIdx.x < 5) {
        int f = f_first + threadIdx.x;
        if (f <= 127)
            compute_frame(logits + ((size_t)(b * NF + f)) * 5, sfr[threadIdx.x]);
    } else if (threadIdx.x == 5) {
        float f0 = f0_hz[b];
        sbp[0] = __fdiv_rn(f0, SRf);                                   // inc
        sbp[1] = phasep[b];                                            // phase
        float partials = __fdiv_rn(12000.0f, __fmul_rn(f0, log10f(f0)));
        sbp[2] = __fmul_rn(3.14159274101257324f, partials);            // kk
        float sh = shpp[b];
        sbp[3] = sh;                                                   // shp
        sbp[4] = __fsub_rn(1.0f, __fmul_rn(sh, 0.5f));                 // sm
        sbp[5] = gainp[b];                                             // gain
        sbp[6] = durp[b];                                              // dur
        sbp[7] = alphap[b];                                            // alpha
        sbp[8] = __fdiv_rn(1.0f, durp[b]);                             // rdur
    }
    __syncthreads();

    float p_inc = sbp[0], p_phase = sbp[1], p_kk = sbp[2], p_shp = sbp[3];
    float p_sm = sbp[4], p_gain = sbp[5], p_dur = sbp[6], p_alpha = sbp[7], p_rdur = sbp[8];

    float pos0 = __fmul_rn((float)s0, POSC);
    int i0s = min((int)floorf(pos0), 126);
    int r0i = i0s - f_first;                    // 0..2
    int r2i = min(i0s + 2, 127) - f_first;      // <=4
    float F0[5], F1[5], F2[5];
#pragma unroll
    for (int q = 0; q < 5; q++) { F0[q] = sfr[r0i][q]; F1[q] = sfr[r0i + 1][q]; F2[q] = sfr[r2i][q]; }

    float yp1 = 0.f, yp2 = 0.f, u1 = 1.f, u2 = 0.f, v1 = 0.f, v2 = 1.f;
    float dryv[8], envv[8], a1v[8], a2v[8], b0v[8], b1v[8], b2v[8];

    float tt0 = div_cr((float)s0, SRf, R48);
    bool alive = (tt0 <= p_dur);

    if (alive) {
        float inc = p_inc;
        float i4 = inc * 4.0f, i2 = inc * 2.0f;
        float baseA = (s0 == 0) ? 0.0f : cum_base3(inc, (unsigned)s0);
        float baseB = cum_base3(inc, (unsigned)(s0 + 8));
#pragma unroll
        for (int j = 0; j < 8; j++) {
            int i = s0 + j;
            unsigned l = (unsigned)(j + 1);
            float cum = (l < 8u) ? baseA : baseB;
            if (l & 4u)  cum = __fadd_rn(cum, i4);
            if (l & 2u)  cum = __fadd_rn(cum, i2);
            if (l & 1u)  cum = __fadd_rn(cum, inc);
            float arg = __fadd_rn(__fmul_rn(6.28318548202514648f, cum), p_phase);
            float carg = __fmul_rn(arg, 0.5f);
            float kq = rintf(__fmul_rn(carg, 0.15915494309189535f));
            float rr = fmaf(-kq, 6.28318548202514648f, carg);
            float ps, pc; int iq;
            fast_sc(rr, ps, pc, iq);
            float shh = (iq & 1) ? pc : ps; shh = (iq & 2) ? -shh : shh;
            float chh = (iq & 1) ? ps : pc; chh = ((iq + 1) & 2) ? -chh : chh;
            float cc = chh;
            float s = 2.0f * shh * chh;

            float sq = xla_tanh_f(__fmul_rn(__fmul_rn(p_kk, s), 0.5f));
            float vco = __fmul_rn(__fmul_rn(p_sm, sq),
                                  __fadd_rn(1.0f, __fmul_rn(p_shp, cc)));

            float tt = div_cr((float)i, SRf, R48);
            float ramp = __fsub_rn(1.0f, div_cr(tt, p_dur, p_rdur));
            ramp = fminf(fmaxf(ramp, 0.001f), 1.0f);
            float env = __powf(ramp, p_alpha);
            if (!(tt <= p_dur)) env = 0.0f;
            envv[j] = env;
            dryv[j] = __fmul_rn(__fmul_rn(vco, p_gain), env);

            float pos = __fmul_rn((float)i, POSC);
            int i0 = min((int)floorf(pos), 126);
            float frc = __fsub_rn(pos, (float)i0);
            float w0 = __fsub_rn(1.0f, frc);
            bool hi = (i0 != i0s);
            float fa1 = hi ? F1[0] : F0[0], ga1 = hi ? F2[0] : F1[0];
            float fa2 = hi ? F1[1] : F0[1], ga2 = hi ? F2[1] : F1[1];
            float fb0 = hi ? F1[2] : F0[2], gb0 = hi ? F2[2] : F1[2];
            float fb1 = hi ? F1[3] : F0[3], gb1 = hi ? F2[3] : F1[3];
            float fb2 = hi ? F1[4] : F0[4], gb2 = hi ? F2[4] : F1[4];
            float a1 = __fadd_rn(__fmul_rn(fa1, w0), __fmul_rn(ga1, frc));
            float a2 = __fadd_rn(__fmul_rn(fa2, w0), __fmul_rn(ga2, frc));
            a1v[j] = a1; a2v[j] = a2;
            b0v[j] = __fadd_rn(__fmul_rn(fb0, w0), __fmul_rn(gb0, frc));
            b1v[j] = __fadd_rn(__fmul_rn(fb1, w0), __fmul_rn(gb1, frc));
            b2v[j] = __fadd_rn(__fmul_rn(fb2, w0), __fmul_rn(gb2, frc));

            float dj = dryv[j];
            float yp = fmaf(-a1, yp1, fmaf(-a2, yp2, dj));
            float uu = fmaf(-a1, u1, -(a2 * u2));
            float vv = fmaf(-a1, v1, -(a2 * v2));
            yp2 = yp1; yp1 = yp;
            u2 = u1; u1 = uu;
            v2 = v1; v1 = vv;
        }
    } else {
#pragma unroll
        for (int j = 0; j < 8; j++) {
            int i = s0 + j;
            envv[j] = 0.0f;
            dryv[j] = 0.0f;
            float pos = __fmul_rn((float)i, POSC);
            int i0 = min((int)floorf(pos), 126);
            float frc = __fsub_rn(pos, (float)i0);
            float w0 = __fsub_rn(1.0f, frc);
            bool hi = (i0 != i0s);
            float fa1 = hi ? F1[0] : F0[0], ga1 = hi ? F2[0] : F1[0];
            float fa2 = hi ? F1[1] : F0[1], ga2 = hi ? F2[1] : F1[1];
            float fb0 = hi ? F1[2] : F0[2], gb0 = hi ? F2[2] : F1[2];
            float fb1 = hi ? F1[3] : F0[3], gb1 = hi ? F2[3] : F1[3];
            float fb2 = hi ? F1[4] : F0[4], gb2 = hi ? F2[4] : F1[4];
            float a1 = __fadd_rn(__fmul_rn(fa1, w0), __fmul_rn(ga1, frc));
            float a2 = __fadd_rn(__fmul_rn(fa2, w0), __fmul_rn(ga2, frc));
            a1v[j] = a1; a2v[j] = a2;
            b0v[j] = __fadd_rn(__fmul_rn(fb0, w0), __fmul_rn(gb0, frc));
            b1v[j] = __fadd_rn(__fmul_rn(fb1, w0), __fmul_rn(gb1, frc));
            b2v[j] = __fadd_rn(__fmul_rn(fb2, w0), __fmul_rn(gb2, frc));

            float uu = fmaf(-a1, u1, -(a2 * u2));
            float vv = fmaf(-a1, v1, -(a2 * v2));
            u2 = u1; u1 = uu;
            v2 = v1; v1 = vv;
        }
        yp1 = 0.f; yp2 = 0.f;
    }

    size_t base = (size_t)b * NS + s0;
    float4* dptr = (float4*)(out + base);
    dptr[0] = make_float4(dryv[0], dryv[1], dryv[2], dryv[3]);
    dptr[1] = make_float4(dryv[4], dryv[5], dryv[6], dryv[7]);
    float4* eptr = (float4*)(out + 2ull * BS * NS + base);
    eptr[0] = make_float4(envv[0], envv[1], envv[2], envv[3]);
    eptr[1] = make_float4(envv[4], envv[5], envv[6], envv[7]);
    float4* aptr = (float4*)(out + 4ull * BS * NS + base * 3);
    aptr[0] = make_float4(1.0f, a1v[0], a2v[0], 1.0f);
    aptr[1] = make_float4(a1v[1], a2v[1], 1.0f, a1v[2]);
    aptr[2] = make_float4(a2v[2], 1.0f, a1v[3], a2v[3]);
    aptr[3] = make_float4(1.0f, a1v[4], a2v[4], 1.0f);
    aptr[4] = make_float4(a1v[5], a2v[5], 1.0f, a1v[6]);
    aptr[5] = make_float4(a2v[6], 1.0f, a1v[7], a2v[7]);
    float4* bptr = (float4*)(out + 7ull * BS * NS + base * 3);
    bptr[0] = make_float4(b0v[0], b1v[0], b2v[0], b0v[1]);
    bptr[1] = make_float4(b1v[1], b2v[1], b0v[2], b1v[2]);
    bptr[2] = make_float4(b2v[2], b0v[3], b1v[3], b2v[3]);
    bptr[3] = make_float4(b0v[4], b1v[4], b2v[4], b0v[5]);
    bptr[4] = make_float4(b1v[5], b2v[5], b0v[6], b1v[6]);
    bptr[5] = make_float4(b2v[6], b0v[7], b1v[7], b2v[7]);

    float* o = g_chunk + (size_t)tid * 6;
    o[0] = u1; o[1] = v1; o[2] = u2; o[3] = v2; o[4] = yp1; o[5] = yp2;
}

// affine compose into explicit accumulator (acc = C ∘ acc; C applied after acc)
#define COMPOSE_ACC(c00,c01,c10,c11,r0,r1, m00,m01,m10,m11,p0,p1) do { \
    float n00 = __fmaf_rn(c00, m00, __fmul_rn(c01, m10)); \
    float n01 = __fmaf_rn(c00, m01, __fmul_rn(c01, m11)); \
    float n10 = __fmaf_rn(c10, m00, __fmul_rn(c11, m10)); \
    float n11 = __fmaf_rn(c10, m01, __fmul_rn(c11, m11)); \
    float np0 = __fadd_rn(__fmaf_rn(c00, p0, __fmul_rn(c01, p1)), r0); \
    float np1 = __fadd_rn(__fmaf_rn(c10, p0, __fmul_rn(c11, p1)), r1); \
    m00 = n00; m01 = n01; m10 = n10; m11 = n11; p0 = np0; p1 = np1; } while (0)

// ---------------- K2: per-voice parallel scan + g_frame publish ----------------
__global__ void k_scan2(const float* __restrict__ logits) {
    extern __shared__ float sm[];          // NCH*7 staging, swapped layout
    __shared__ float wtot[8 * 6];
    __shared__ float wpre[8 * 6];
    int b = blockIdx.x;
    int tid = threadIdx.x;

    const float* raw = g_chunk + (size_t)b * NCH * 6;
    for (int idx = tid; idx < NCH * 6; idx += blockDim.x) {
        int chunk = idx / 6;
        int field = idx - chunk * 6;
        int w = chunk >> 10;
        int chr = chunk & 1023;
        int swp = ((chr & 31) << 5) | (chr >> 5);
        sm[((w << 10) + swp) * 7 + field] = raw[idx];
    }
    // idle warps publish g_frame for pass2 (independent of scan data)
    if (tid >= 256 && tid < 384) {
        int f = tid - 256;
        float dst[5];
        compute_frame(logits + ((size_t)(b * NF + f)) * 5, dst);
        g_frame[(b * NF + f) * 2]     = make_float4(dst[0], dst[1], dst[2], dst[3]);
        g_frame[(b * NF + f) * 2 + 1] = make_float4(dst[4], 0.f, 0.f, 0.f);
    }
    __syncthreads();

    float m00 = 1.f, m01 = 0.f, m10 = 0.f, m11 = 1.f, p0 = 0.f, p1 = 0.f;
    int w = tid >> 5, lane = tid & 31;
    if (tid < 256) {
        const float* rbase = &sm[(w << 10) * 7 + lane * 7];
#pragma unroll 1
        for (int c = 0; c < 32; c++) {
            const float* rec = rbase + (c << 5) * 7;
            COMPOSE_ACC(rec[0], rec[1], rec[2], rec[3], rec[4], rec[5],
                        m00, m01, m10, m11, p0, p1);
        }
        // inclusive Kogge-Stone across lanes: m = m ∘ e (current AFTER earlier)
#pragma unroll
        for (int d = 1; d < 32; d <<= 1) {
            float e00 = __shfl_up_sync(0xffffffffu, m00, d);
            float e01 = __shfl_up_sync(0xffffffffu, m01, d);
            float e10 = __shfl_up_sync(0xffffffffu, m10, d);
            float e11 = __shfl_up_sync(0xffffffffu, m11, d);
            float ep0 = __shfl_up_sync(0xffffffffu, p0, d);
            float ep1 = __shfl_up_sync(0xffffffffu, p1, d);
            if (lane >= d) {
                float n00 = __fmaf_rn(m00, e00, __fmul_rn(m01, e10));
                float n01 = __fmaf_rn(m00, e01, __fmul_rn(m01, e11));
                float n10 = __fmaf_rn(m10, e00, __fmul_rn(m11, e10));
                float n11 = __fmaf_rn(m10, e01, __fmul_rn(m11, e11));
                float np0 = __fadd_rn(__fmaf_rn(m00, ep0, __fmul_rn(m01, ep1)), p0);
                float np1 = __fadd_rn(__fmaf_rn(m10, ep0, __fmul_rn(m11, ep1)), p1);
                m00 = n00; m01 = n01; m10 = n10; m11 = n11; p0 = np0; p1 = np1;
            }
        }
        if (lane == 31) {
            wtot[w * 6 + 0] = m00; wtot[w * 6 + 1] = m01; wtot[w * 6 + 2] = m10;
            wtot[w * 6 + 3] = m11; wtot[w * 6 + 4] = p0;  wtot[w * 6 + 5] = p1;
        }
    }
    __syncthreads();
    if (tid == 0) {
        float q00 = 1.f, q01 = 0.f, q10 = 0.f, q11 = 1.f, qp0 = 0.f, qp1 = 0.f;
#pragma unroll
        for (int ww = 0; ww < 8; ww++) {
            wpre[ww * 6 + 0] = q00; wpre[ww * 6 + 1] = q01; wpre[ww * 6 + 2] = q10;
            wpre[ww * 6 + 3] = q11; wpre[ww * 6 + 4] = qp0; wpre[ww * 6 + 5] = qp1;
            COMPOSE_ACC(wtot[ww * 6 + 0], wtot[ww * 6 + 1], wtot[ww * 6 + 2],
                        wtot[ww * 6 + 3], wtot[ww * 6 + 4], wtot[ww * 6 + 5],
                        q00, q01, q10, q11, qp0, qp1);
        }
    }
    __syncthreads();
    if (tid < 256) {
        // within-warp exclusive affine (from inclusive values)
        float e00 = __shfl_up_sync(0xffffffffu, m00, 1);
        float e01 = __shfl_up_sync(0xffffffffu, m01, 1);
        float e10 = __shfl_up_sync(0xffffffffu, m10, 1);
        float e11 = __shfl_up_sync(0xffffffffu, m11, 1);
        float ep0 = __shfl_up_sync(0xffffffffu, p0, 1);
        float ep1 = __shfl_up_sync(0xffffffffu, p1, 1);
        if (lane == 0) { e00 = 1.f; e01 = 0.f; e10 = 0.f; e11 = 1.f; ep0 = 0.f; ep1 = 0.f; }
        // state entering this lane's group: s = E · (warp-prefix state) + E.p
        float Pp0 = wpre[w * 6 + 4], Pp1 = wpre[w * 6 + 5];
        float s0 = __fadd_rn(__fmaf_rn(e00, Pp0, __fmul_rn(e01, Pp1)), ep0);
        float s1 = __fadd_rn(__fmaf_rn(e10, Pp0, __fmul_rn(e11, Pp1)), ep1);

        const float* rbase = &sm[(w << 10) * 7 + lane * 7];
        int cbase = (b << 13) + tid * 32;
#pragma unroll 1
        for (int c = 0; c < 32; c++) {
            g_init[cbase + c] = make_float2(s0, s1);
            const float* rec = rbase + (c << 5) * 7;
            float ns0 = __fadd_rn(__fmaf_rn(rec[0], s0, __fmul_rn(rec[1], s1)), rec[4]);
            float ns1 = __fadd_rn(__fmaf_rn(rec[2], s0, __fmul_rn(rec[3], s1)), rec[5]);
            s0 = ns0; s1 = ns1;
        }
    }
}

// ---------------- K3: pass 2 — coeff recompute + IIR + FIR + tanh ----------------
__global__ void k_pass2(float* __restrict__ out, const float* __restrict__ distp) {
    int tid = blockIdx.x * blockDim.x + threadIdx.x;
    if (tid >= BS * NCH) return;
    int b = tid >> 13;
    int c = tid & (NCH - 1);
    int s0 = c << 3;
    size_t base = (size_t)b * NS + s0;
    const float* dry = out + base;
    float* w_wet = out + 1ull * BS * NS + base;
    float* w_yab = out + 3ull * BS * NS + base;
    float* w_ya = out + 10ull * BS * NS + base;

    float pos0 = __fmul_rn((float)s0, POSC);
    int i0s = min((int)floorf(pos0), 126);
    int i2x = min(i0s + 2, 127);
    float4 F0a = g_frame[(b * NF + i0s) * 2],     F0b = g_frame[(b * NF + i0s) * 2 + 1];
    float4 F1a = g_frame[(b * NF + i0s + 1) * 2], F1b = g_frame[(b * NF + i0s + 1) * 2 + 1];
    float4 F2a = g_frame[(b * NF + i2x) * 2],     F2b = g_frame[(b * NF + i2x) * 2 + 1];

    float2 ini = g_init[tid];
    float y1 = ini.x, y2 = ini.y;
    float dg = distp[b];

    float4 x0 = *(const float4*)(dry);
    float4 x1 = *(const float4*)(dry + 4);
    float xs[8] = {x0.x, x0.y, x0.z, x0.w, x1.x, x1.y, x1.z, x1.w};
    float ya[8], yb[8], wt[8];
#pragma unroll
    for (int j = 0; j < 8; j++) {
        int i = s0 + j;
        float pos = __fmul_rn((float)i, POSC);
        int i0 = min((int)floorf(pos), 126);
        float frc = __fsub_rn(pos, (float)i0);
        float w0 = __fsub_rn(1.0f, frc);
        bool hi = (i0 != i0s);
        float4 fA = hi ? F1a : F0a;
        float4 fB = hi ? F1b : F0b;
        float4 gA = hi ? F2a : F1a;
        float4 gB = hi ? F2b : F1b;
        float a1 = __fadd_rn(__fmul_rn(fA.x, w0), __fmul_rn(gA.x, frc));
        float a2 = __fadd_rn(__fmul_rn(fA.y, w0), __fmul_rn(gA.y, frc));
        float c0 = __fadd_rn(__fmul_rn(fA.z, w0), __fmul_rn(gA.z, frc));
        float c1 = __fadd_rn(__fmul_rn(fA.w, w0), __fmul_rn(gA.w, frc));
        float c2 = __fadd_rn(__fmul_rn(fB.x, w0), __fmul_rn(gB.x, frc));

        float y = __fsub_rn(__fsub_rn(xs[j], __fmul_rn(a1, y1)), __fmul_rn(a2, y2));
        float v = __fadd_rn(__fadd_rn(__fmul_rn(c0, y), __fmul_rn(c1, y1)),
                            __fmul_rn(c2, y2));
        ya[j] = y; yb[j] = v;
        wt[j] = xla_tanh_f(__fmul_rn(v, dg));
        y2 = y1; y1 = y;
    }
    ((float4*)w_ya)[0] = make_float4(ya[0], ya[1], ya[2], ya[3]);
    ((float4*)w_ya)[1] = make_float4(ya[4], ya[5], ya[6], ya[7]);
    ((float4*)w_yab)[0] = make_float4(yb[0], yb[1], yb[2], yb[3]);
    ((float4*)w_yab)[1] = make_float4(yb[4], yb[5], yb[6], yb[7]);
    ((float4*)w_wet)[0] = make_float4(wt[0], wt[1], wt[2], wt[3]);
    ((float4*)w_wet)[1] = make_float4(wt[4], wt[5], wt[6], wt[7]);
}

extern "C" void kernel_launch(void* const* d_in, const int* in_sizes, int n_in,
                              void* d_out, int out_size) {
    const float* f0_hz = (const float*)d_in[0];
    const float* note_on = (const float*)d_in[1];
    const float* phase = (const float*)d_in[2];
    const float* logits = (const float*)d_in[3];
    const float* osc_shape = (const float*)d_in[4];
    const float* osc_gain = (const float*)d_in[5];
    const float* dist_gain = (const float*)d_in[6];
    const float* learned_alpha = (const float*)d_in[7];
    float* out = (float*)d_out;

    static int smem_set = 0;
    const int scan_smem = NCH * 7 * sizeof(float);   // 229376 B dynamic
    if (!smem_set) {
        cudaFuncSetAttribute(k_scan2, cudaFuncAttributeMaxDynamicSharedMemorySize, scan_smem);
        smem_set = 1;
    }

    k_mainp1<<<(BS * NCH + 127) / 128, 128>>>(out, f0_hz, note_on, phase, logits,
                                              osc_shape, osc_gain, learned_alpha);
    k_scan2<<<BS, 1024, scan_smem>>>(logits);
    k_pass2<<<(BS * NCH + 127) / 128, 128>>>(out, dist_gain);
}

// round 14
// speedup vs baseline: 1.2086x; 1.0011x over previous
#include <cuda_runtime.h>
#include <math.h>
#include <stdint.h>

#define BS 32
#define NS 65536
#define NF 128
#define CHUNK 8
#define NCH (NS / CHUNK)      // 8192
#define SRf 48000.0f
#define STAB 0.999f
#define POSC (127.0f / 65535.0f)
#define R48 (1.0f / 48000.0f)

// Output plane offsets (elements of BS*NS):
// dry=0, wet=1, env=2, y_ab=3, a_coeff3=4..6, b_coeff=7..9, y_a=10

__device__ float4 g_frame[BS * NF * 2];
__device__ float  g_chunk[BS * NCH * 6];  // u1,v1,u2,v2,yp1,yp2
__device__ float2 g_init[BS * NCH];

__device__ __forceinline__ float div_cr(float x, float d, float r) {
    float q0 = __fmul_rn(x, r);
    float rem = fmaf(-q0, d, x);
    return fmaf(rem, r, q0);
}

// ---- XLA rational tanh: CR-div version (coeff path) ----
__device__ __forceinline__ float xla_tanh_cr(float x) {
    const float kClamp = 7.90531110763549805f;
    float xc = fminf(fmaxf(x, -kClamp), kClamp);
    float x2 = __fmul_rn(xc, xc);
    float p = __fadd_rn(2.00018790482477e-13f, __fmul_rn(x2, -2.76076847742355e-16f));
    p = __fadd_rn(-8.60467152213735e-11f, __fmul_rn(x2, p));
    p = __fadd_rn(5.12229709037114e-08f,  __fmul_rn(x2, p));
    p = __fadd_rn(1.48572235717979e-05f,  __fmul_rn(x2, p));
    p = __fadd_rn(6.37261928875436e-04f,  __fmul_rn(x2, p));
    p = __fadd_rn(4.89352455891786e-03f,  __fmul_rn(x2, p));
    float num = __fmul_rn(xc, p);
    float q = __fadd_rn(1.18534705686654e-04f, __fmul_rn(x2, 1.19825839466702e-06f));
    q = __fadd_rn(2.26843463243900e-03f, __fmul_rn(x2, q));
    q = __fadd_rn(4.89352518554385e-03f, __fmul_rn(x2, q));
    float r = __fdiv_rn(num, q);
    return (fabsf(x) < 0.0004f) ? x : r;
}

// ---- fast-div version (per-sample path; ~2ulp) ----
__device__ __forceinline__ float xla_tanh_f(float x) {
    const float kClamp = 7.90531110763549805f;
    float xc = fminf(fmaxf(x, -kClamp), kClamp);
    float x2 = __fmul_rn(xc, xc);
    float p = __fadd_rn(2.00018790482477e-13f, __fmul_rn(x2, -2.76076847742355e-16f));
    p = __fadd_rn(-8.60467152213735e-11f, __fmul_rn(x2, p));
    p = __fadd_rn(5.12229709037114e-08f,  __fmul_rn(x2, p));
    p = __fadd_rn(1.48572235717979e-05f,  __fmul_rn(x2, p));
    p = __fadd_rn(6.37261928875436e-04f,  __fmul_rn(x2, p));
    p = __fadd_rn(4.89352455891786e-03f,  __fmul_rn(x2, p));
    float num = __fmul_rn(xc, p);
    float q = __fadd_rn(1.18534705686654e-04f, __fmul_rn(x2, 1.19825839466702e-06f));
    q = __fadd_rn(2.26843463243900e-03f, __fmul_rn(x2, q));
    q = __fadd_rn(4.89352518554385e-03f, __fmul_rn(x2, q));
    float r = __fdividef(num, q);
    return (fabsf(x) < 0.0004f) ? x : r;
}

__device__ __forceinline__ void fast_sc(float r, float& ps, float& pc, int& iq) {
    float qf = rintf(r * 0.636619772367581343f);
    float t = fmaf(qf, -1.57079637050628662109f, r);
    t = fmaf(qf, 4.37113900018624283e-8f, t);
    iq = ((int)qf) & 3;
    float t2 = t * t;
    float s = fmaf(t2, 2.7557314297e-06f, -1.9841270114e-04f);
    s = fmaf(t2, s, 8.3333337680e-03f);
    s = fmaf(t2, s, -1.6666667163e-01f);
    ps = fmaf(t * t2, s, t);
    float c = fmaf(t2, 2.4801587642e-05f, -1.3888889225e-03f);
    c = fmaf(t2, c, 4.1666667908e-02f);
    c = fmaf(t2, c, -0.5f);
    pc = fmaf(t2, c, 1.0f);
}

__device__ __forceinline__ float cum_base3(float c, unsigned v) {
    int msb = 31 - __clz(v);
    float r = c * __int_as_float((127 + msb) << 23);
#pragma unroll 1
    for (int k = msb - 1; k >= 3; k--) {
        if ((v >> k) & 1u)
            r = __fadd_rn(r, c * __int_as_float((127 + k) << 23));
    }
    return r;
}

__device__ __forceinline__ void compute_frame(const float* __restrict__ lg, float* dst) {
    float th0 = xla_tanh_cr(lg[0]);
    float a1 = __fmul_rn(__fmul_rn(2.0f, th0), STAB);
    float a1a = fabsf(a1);
    float th1 = xla_tanh_cr(lg[1]);
    float a2 = __fdiv_rn(__fadd_rn(__fmul_rn(__fmul_rn(__fsub_rn(2.0f, a1a), th1), STAB), a1a), 2.0f);
    dst[0] = a1; dst[1] = a2; dst[2] = lg[2]; dst[3] = lg[3]; dst[4] = lg[4];
}

// ---------------- K1: osc + env + coeff interp + fused pass1 ----------------
__global__ void __launch_bounds__(128) k_mainp1(
        float* __restrict__ out,
        const float* __restrict__ f0_hz,
        const float* __restrict__ durp,
        const float* __restrict__ phasep,
        const float* __restrict__ logits,
        const float* __restrict__ shpp,
        const float* __restrict__ gainp,
        const float* __restrict__ alphap) {
    __shared__ float sfr[5][5];
    __shared__ float sbp[12];

    int tid = blockIdx.x * blockDim.x + threadIdx.x;
    int b = tid >> 13;
    int c = tid & (NCH - 1);
    int s0 = c << 3;

    int BS0 = (blockIdx.x & 63) << 10;
    float bpos0 = __fmul_rn((float)BS0, POSC);
    int f_first = min((int)floorf(bpos0), 126);

    if (threadIdx.x < 5) {
        int f = f_first + threadIdx.x;
        if (f <= 127)
            compute_frame(logits + ((size_t)(b * NF + f)) * 5, sfr[threadIdx.x]);
    } else if (threadIdx.x == 5) {
        float f0 = f0_hz[b];
        sbp[0] = __fdiv_rn(f0, SRf);
        sbp[1] = phasep[b];
        float partials = __fdiv_rn(12000.0f, __fmul_rn(f0, log10f(f0)));
        sbp[2] = __fmul_rn(3.14159274101257324f, partials);
        float sh = shpp[b];
        sbp[3] = sh;
        sbp[4] = __fsub_rn(1.0f, __fmul_rn(sh, 0.5f));
        sbp[5] = gainp[b];
        sbp[6] = durp[b];
        sbp[7] = alphap[b];
        sbp[8] = __fdiv_rn(1.0f, durp[b]);
    }
    __syncthreads();

    float p_inc = sbp[0], p_phase = sbp[1], p_kk = sbp[2], p_shp = sbp[3];
    float p_sm = sbp[4], p_gain = sbp[5], p_dur = sbp[6], p_alpha = sbp[7], p_rdur = sbp[8];

    float pos0 = __fmul_rn((float)s0, POSC);
    int i0s = min((int)floorf(pos0), 126);
    int r0i = i0s - f_first;
    int r2i = min(i0s + 2, 127) - f_first;
    float F0[5], F1[5], F2[5];
#pragma unroll
    for (int q = 0; q < 5; q++) { F0[q] = sfr[r0i][q]; F1[q] = sfr[r0i + 1][q]; F2[q] = sfr[r2i][q]; }

    float yp1 = 0.f, yp2 = 0.f, u1 = 1.f, u2 = 0.f, v1 = 0.f, v2 = 1.f;

    float tt0 = div_cr((float)s0, SRf, R48);
    bool alive = (tt0 <= p_dur);

    size_t base = (size_t)b * NS + s0;
    float4* dptr = (float4*)(out + base);
    float4* eptr = (float4*)(out + 2ull * BS * NS + base);
    float4* aptr = (float4*)(out + 4ull * BS * NS + base * 3);
    float4* bptr = (float4*)(out + 7ull * BS * NS + base * 3);

    float inc = p_inc;
    float i4 = inc * 4.0f, i2c = inc * 2.0f;
    float baseA = 0.0f, baseB = 0.0f;
    if (alive) {
        baseA = (s0 == 0) ? 0.0f : cum_base3(inc, (unsigned)s0);
        baseB = cum_base3(inc, (unsigned)(s0 + 8));
    }

#pragma unroll
    for (int g = 0; g < 2; g++) {
        float dry4[4], env4[4], a1v[4], a2v[4], b0v[4], b1v[4], b2v[4];
#pragma unroll
        for (int j = 0; j < 4; j++) {
            int jj = g * 4 + j;
            int i = s0 + jj;
            if (alive) {
                unsigned l = (unsigned)(jj + 1);
                float cum = (l < 8u) ? baseA : baseB;
                if (l & 4u)  cum = __fadd_rn(cum, i4);
                if (l & 2u)  cum = __fadd_rn(cum, i2c);
                if (l & 1u)  cum = __fadd_rn(cum, inc);
                float arg = __fadd_rn(__fmul_rn(6.28318548202514648f, cum), p_phase);
                float carg = __fmul_rn(arg, 0.5f);
                float kq = rintf(__fmul_rn(carg, 0.15915494309189535f));
                float rr = fmaf(-kq, 6.28318548202514648f, carg);
                float ps, pc; int iq;
                fast_sc(rr, ps, pc, iq);
                float shh = (iq & 1) ? pc : ps; shh = (iq & 2) ? -shh : shh;
                float chh = (iq & 1) ? ps : pc; chh = ((iq + 1) & 2) ? -chh : chh;
                float cc = chh;
                float s = 2.0f * shh * chh;

                float sq = xla_tanh_f(__fmul_rn(__fmul_rn(p_kk, s), 0.5f));
                float vco = __fmul_rn(__fmul_rn(p_sm, sq),
                                      __fadd_rn(1.0f, __fmul_rn(p_shp, cc)));

                float tt = div_cr((float)i, SRf, R48);
                float ramp = __fsub_rn(1.0f, div_cr(tt, p_dur, p_rdur));
                ramp = fminf(fmaxf(ramp, 0.001f), 1.0f);
                float env = __powf(ramp, p_alpha);
                if (!(tt <= p_dur)) env = 0.0f;
                env4[j] = env;
                dry4[j] = __fmul_rn(__fmul_rn(vco, p_gain), env);
            } else {
                env4[j] = 0.0f;
                dry4[j] = 0.0f;
            }

            float pos = __fmul_rn((float)i, POSC);
            int i0 = min((int)floorf(pos), 126);
            float frc = __fsub_rn(pos, (float)i0);
            float w0 = __fsub_rn(1.0f, frc);
            bool hi = (i0 != i0s);
            float fa1 = hi ? F1[0] : F0[0], ga1 = hi ? F2[0] : F1[0];
            float fa2 = hi ? F1[1] : F0[1], ga2 = hi ? F2[1] : F1[1];
            float fb0 = hi ? F1[2] : F0[2], gb0 = hi ? F2[2] : F1[2];
            float fb1 = hi ? F1[3] : F0[3], gb1 = hi ? F2[3] : F1[3];
            float fb2 = hi ? F1[4] : F0[4], gb2 = hi ? F2[4] : F1[4];
            float a1 = __fadd_rn(__fmul_rn(fa1, w0), __fmul_rn(ga1, frc));
            float a2 = __fadd_rn(__fmul_rn(fa2, w0), __fmul_rn(ga2, frc));
            a1v[j] = a1; a2v[j] = a2;
            b0v[j] = __fadd_rn(__fmul_rn(fb0, w0), __fmul_rn(gb0, frc));
            b1v[j] = __fadd_rn(__fmul_rn(fb1, w0), __fmul_rn(gb1, frc));
            b2v[j] = __fadd_rn(__fmul_rn(fb2, w0), __fmul_rn(gb2, frc));

            float dj = dry4[j];
            float yp = fmaf(-a1, yp1, fmaf(-a2, yp2, dj));
            float uu = fmaf(-a1, u1, -(a2 * u2));
            float vv = fmaf(-a1, v1, -(a2 * v2));
            yp2 = yp1; yp1 = yp;
            u2 = u1; u1 = uu;
            v2 = v1; v1 = vv;
        }
        // immediate stores for this 4-sample group
        dptr[g] = make_float4(dry4[0], dry4[1], dry4[2], dry4[3]);
        eptr[g] = make_float4(env4[0], env4[1], env4[2], env4[3]);
        aptr[3 * g + 0] = make_float4(1.0f, a1v[0], a2v[0], 1.0f);
        aptr[3 * g + 1] = make_float4(a1v[1], a2v[1], 1.0f, a1v[2]);
        aptr[3 * g + 2] = make_float4(a2v[2], 1.0f, a1v[3], a2v[3]);
        bptr[3 * g + 0] = make_float4(b0v[0], b1v[0], b2v[0], b0v[1]);
        bptr[3 * g + 1] = make_float4(b1v[1], b2v[1], b0v[2], b1v[2]);
        bptr[3 * g + 2] = make_float4(b2v[2], b0v[3], b1v[3], b2v[3]);
    }

    float* o = g_chunk + (size_t)tid * 6;
    o[0] = u1; o[1] = v1; o[2] = u2; o[3] = v2; o[4] = yp1; o[5] = yp2;
}

// affine compose into explicit accumulator (acc = C ∘ acc)
#define COMPOSE_ACC(c00,c01,c10,c11,r0,r1, m00,m01,m10,m11,p0,p1) do { \
    float n00 = __fmaf_rn(c00, m00, __fmul_rn(c01, m10)); \
    float n01 = __fmaf_rn(c00, m01, __fmul_rn(c01, m11)); \
    float n10 = __fmaf_rn(c10, m00, __fmul_rn(c11, m10)); \
    float n11 = __fmaf_rn(c10, m01, __fmul_rn(c11, m11)); \
    float np0 = __fadd_rn(__fmaf_rn(c00, p0, __fmul_rn(c01, p1)), r0); \
    float np1 = __fadd_rn(__fmaf_rn(c10, p0, __fmul_rn(c11, p1)), r1); \
    m00 = n00; m01 = n01; m10 = n10; m11 = n11; p0 = np0; p1 = np1; } while (0)

// ---------------- K2: per-voice parallel scan + g_frame publish ----------------
__global__ void k_scan2(const float* __restrict__ logits) {
    extern __shared__ float sm[];
    __shared__ float wtot[8 * 6];
    __shared__ float wpre[8 * 6];
    int b = blockIdx.x;
    int tid = threadIdx.x;

    const float* raw = g_chunk + (size_t)b * NCH * 6;
    for (int idx = tid; idx < NCH * 6; idx += blockDim.x) {
        int chunk = idx / 6;
        int field = idx - chunk * 6;
        int w = chunk >> 10;
        int chr = chunk & 1023;
        int swp = ((chr & 31) << 5) | (chr >> 5);
        sm[((w << 10) + swp) * 7 + field] = raw[idx];
    }
    if (tid >= 256 && tid < 384) {
        int f = tid - 256;
        float dst[5];
        compute_frame(logits + ((size_t)(b * NF + f)) * 5, dst);
        g_frame[(b * NF + f) * 2]     = make_float4(dst[0], dst[1], dst[2], dst[3]);
        g_frame[(b * NF + f) * 2 + 1] = make_float4(dst[4], 0.f, 0.f, 0.f);
    }
    __syncthreads();

    float m00 = 1.f, m01 = 0.f, m10 = 0.f, m11 = 1.f, p0 = 0.f, p1 = 0.f;
    int w = tid >> 5, lane = tid & 31;
    if (tid < 256) {
        const float* rbase = &sm[(w << 10) * 7 + lane * 7];
#pragma unroll 1
        for (int c = 0; c < 32; c++) {
            const float* rec = rbase + (c << 5) * 7;
            COMPOSE_ACC(rec[0], rec[1], rec[2], rec[3], rec[4], rec[5],
                        m00, m01, m10, m11, p0, p1);
        }
#pragma unroll
        for (int d = 1; d < 32; d <<= 1) {
            float e00 = __shfl_up_sync(0xffffffffu, m00, d);
            float e01 = __shfl_up_sync(0xffffffffu, m01, d);
            float e10 = __shfl_up_sync(0xffffffffu, m10, d);
            float e11 = __shfl_up_sync(0xffffffffu, m11, d);
            float ep0 = __shfl_up_sync(0xffffffffu, p0, d);
            float ep1 = __shfl_up_sync(0xffffffffu, p1, d);
            if (lane >= d) {
                float n00 = __fmaf_rn(m00, e00, __fmul_rn(m01, e10));
                float n01 = __fmaf_rn(m00, e01, __fmul_rn(m01, e11));
                float n10 = __fmaf_rn(m10, e00, __fmul_rn(m11, e10));
                float n11 = __fmaf_rn(m10, e01, __fmul_rn(m11, e11));
                float np0 = __fadd_rn(__fmaf_rn(m00, ep0, __fmul_rn(m01, ep1)), p0);
                float np1 = __fadd_rn(__fmaf_rn(m10, ep0, __fmul_rn(m11, ep1)), p1);
                m00 = n00; m01 = n01; m10 = n10; m11 = n11; p0 = np0; p1 = np1;
            }
        }
        if (lane == 31) {
            wtot[w * 6 + 0] = m00; wtot[w * 6 + 1] = m01; wtot[w * 6 + 2] = m10;
            wtot[w * 6 + 3] = m11; wtot[w * 6 + 4] = p0;  wtot[w * 6 + 5] = p1;
        }
    }
    __syncthreads();
    if (tid == 0) {
        float q00 = 1.f, q01 = 0.f, q10 = 0.f, q11 = 1.f, qp0 = 0.f, qp1 = 0.f;
#pragma unroll
        for (int ww = 0; ww < 8; ww++) {
            wpre[ww * 6 + 0] = q00; wpre[ww * 6 + 1] = q01; wpre[ww * 6 + 2] = q10;
            wpre[ww * 6 + 3] = q11; wpre[ww * 6 + 4] = qp0; wpre[ww * 6 + 5] = qp1;
            COMPOSE_ACC(wtot[ww * 6 + 0], wtot[ww * 6 + 1], wtot[ww * 6 + 2],
                        wtot[ww * 6 + 3], wtot[ww * 6 + 4], wtot[ww * 6 + 5],
                        q00, q01, q10, q11, qp0, qp1);
        }
    }
    __syncthreads();
    if (tid < 256) {
        float e00 = __shfl_up_sync(0xffffffffu, m00, 1);
        float e01 = __shfl_up_sync(0xffffffffu, m01, 1);
        float e10 = __shfl_up_sync(0xffffffffu, m10, 1);
        float e11 = __shfl_up_sync(0xffffffffu, m11, 1);
        float ep0 = __shfl_up_sync(0xffffffffu, p0, 1);
        float ep1 = __shfl_up_sync(0xffffffffu, p1, 1);
        if (lane == 0) { e00 = 1.f; e01 = 0.f; e10 = 0.f; e11 = 1.f; ep0 = 0.f; ep1 = 0.f; }
        float Pp0 = wpre[w * 6 + 4], Pp1 = wpre[w * 6 + 5];
        float s0 = __fadd_rn(__fmaf_rn(e00, Pp0, __fmul_rn(e01, Pp1)), ep0);
        float s1 = __fadd_rn(__fmaf_rn(e10, Pp0, __fmul_rn(e11, Pp1)), ep1);

        const float* rbase = &sm[(w << 10) * 7 + lane * 7];
        int cbase = (b << 13) + tid * 32;
#pragma unroll 1
        for (int c = 0; c < 32; c++) {
            g_init[cbase + c] = make_float2(s0, s1);
            const float* rec = rbase + (c << 5) * 7;
            float ns0 = __fadd_rn(__fmaf_rn(rec[0], s0, __fmul_rn(rec[1], s1)), rec[4]);
            float ns1 = __fadd_rn(__fmaf_rn(rec[2], s0, __fmul_rn(rec[3], s1)), rec[5]);
            s0 = ns0; s1 = ns1;
        }
    }
}

// ---------------- K3: pass 2 — coeff recompute + IIR + FIR + tanh ----------------
__global__ void __launch_bounds__(128) k_pass2(float* __restrict__ out,
                                               const float* __restrict__ distp) {
    int tid = blockIdx.x * blockDim.x + threadIdx.x;
    if (tid >= BS * NCH) return;
    int b = tid >> 13;
    int c = tid & (NCH - 1);
    int s0 = c << 3;
    size_t base = (size_t)b * NS + s0;
    const float* dry = out + base;
    float* w_wet = out + 1ull * BS * NS + base;
    float* w_yab = out + 3ull * BS * NS + base;
    float* w_ya = out + 10ull * BS * NS + base;

    float pos0 = __fmul_rn((float)s0, POSC);
    int i0s = min((int)floorf(pos0), 126);
    int i2x = min(i0s + 2, 127);
    float4 F0a = g_frame[(b * NF + i0s) * 2],     F0b = g_frame[(b * NF + i0s) * 2 + 1];
    float4 F1a = g_frame[(b * NF + i0s + 1) * 2], F1b = g_frame[(b * NF + i0s + 1) * 2 + 1];
    float4 F2a = g_frame[(b * NF + i2x) * 2],     F2b = g_frame[(b * NF + i2x) * 2 + 1];

    float2 ini = g_init[tid];
    float y1 = ini.x, y2 = ini.y;
    float dg = distp[b];

#pragma unroll
    for (int g = 0; g < 2; g++) {
        float4 xq = ((const float4*)dry)[g];
        float xs[4] = {xq.x, xq.y, xq.z, xq.w};
        float ya[4], yb[4], wt[4];
#pragma unroll
        for (int j = 0; j < 4; j++) {
            int i = s0 + g * 4 + j;
            float pos = __fmul_rn((float)i, POSC);
            int i0 = min((int)floorf(pos), 126);
            float frc = __fsub_rn(pos, (float)i0);
            float w0 = __fsub_rn(1.0f, frc);
            bool hi = (i0 != i0s);
            float4 fA = hi ? F1a : F0a;
            float4 fB = hi ? F1b : F0b;
            float4 gA = hi ? F2a : F1a;
            float4 gB = hi ? F2b : F1b;
            float a1 = __fadd_rn(__fmul_rn(fA.x, w0), __fmul_rn(gA.x, frc));
            float a2 = __fadd_rn(__fmul_rn(fA.y, w0), __fmul_rn(gA.y, frc));
            float c0 = __fadd_rn(__fmul_rn(fA.z, w0), __fmul_rn(gA.z, frc));
            float c1 = __fadd_rn(__fmul_rn(fA.w, w0), __fmul_rn(gA.w, frc));
            float c2 = __fadd_rn(__fmul_rn(fB.x, w0), __fmul_rn(gB.x, frc));

            float y = __fsub_rn(__fsub_rn(xs[j], __fmul_rn(a1, y1)), __fmul_rn(a2, y2));
            float v = __fadd_rn(__fadd_rn(__fmul_rn(c0, y), __fmul_rn(c1, y1)),
                                __fmul_rn(c2, y2));
            ya[j] = y; yb[j] = v;
            wt[j] = xla_tanh_f(__fmul_rn(v, dg));
            y2 = y1; y1 = y;
        }
        ((float4*)w_ya)[g] = make_float4(ya[0], ya[1], ya[2], ya[3]);
        ((float4*)w_yab)[g] = make_float4(yb[0], yb[1], yb[2], yb[3]);
        ((float4*)w_wet)[g] = make_float4(wt[0], wt[1], wt[2], wt[3]);
    }
}

extern "C" void kernel_launch(void* const* d_in, const int* in_sizes, int n_in,
                              void* d_out, int out_size) {
    const float* f0_hz = (const float*)d_in[0];
    const float* note_on = (const float*)d_in[1];
    const float* phase = (const float*)d_in[2];
    const float* logits = (const float*)d_in[3];
    const float* osc_shape = (const float*)d_in[4];
    const float* osc_gain = (const float*)d_in[5];
    const float* dist_gain = (const float*)d_in[6];
    const float* learned_alpha = (const float*)d_in[7];
    float* out = (float*)d_out;

    static int smem_set = 0;
    const int scan_smem = NCH * 7 * sizeof(float);   // 229376 B dynamic
    if (!smem_set) {
        cudaFuncSetAttribute(k_scan2, cudaFuncAttributeMaxDynamicSharedMemorySize, scan_smem);
        smem_set = 1;
    }

    k_mainp1<<<(BS * NCH + 127) / 128, 128>>>(out, f0_hz, note_on, phase, logits,
                                              osc_shape, osc_gain, learned_alpha);
    k_scan2<<<BS, 1024, scan_smem>>>(logits);
    k_pass2<<<(BS * NCH + 127) / 128, 128>>>(out, dist_gain);
}

// round 15
// speedup vs baseline: 1.2589x; 1.0417x over previous
#include <cuda_runtime.h>
#include <math.h>
#include <stdint.h>

#define BS 32
#define NS 65536
#define NF 128
#define CHUNK 8
#define NCH (NS / CHUNK)      // 8192
#define SRf 48000.0f
#define STAB 0.999f
#define POSC (127.0f / 65535.0f)
#define R48 (1.0f / 48000.0f)

// Output plane offsets (elements of BS*NS):
// dry=0, wet=1, env=2, y_ab=3, a_coeff3=4..6, b_coeff=7..9, y_a=10

__device__ float4 g_frame[BS * NF * 2];
__device__ float  g_chunk[BS * NCH * 6];  // u1,v1,u2,v2,yp1,yp2
__device__ float2 g_init[BS * NCH];

__device__ __forceinline__ float div_cr(float x, float d, float r) {
    float q0 = __fmul_rn(x, r);
    float rem = fmaf(-q0, d, x);
    return fmaf(rem, r, q0);
}

// ---- XLA rational tanh: CR-div version (coeff path) ----
__device__ __forceinline__ float xla_tanh_cr(float x) {
    const float kClamp = 7.90531110763549805f;
    float xc = fminf(fmaxf(x, -kClamp), kClamp);
    float x2 = __fmul_rn(xc, xc);
    float p = __fadd_rn(2.00018790482477e-13f, __fmul_rn(x2, -2.76076847742355e-16f));
    p = __fadd_rn(-8.60467152213735e-11f, __fmul_rn(x2, p));
    p = __fadd_rn(5.12229709037114e-08f,  __fmul_rn(x2, p));
    p = __fadd_rn(1.48572235717979e-05f,  __fmul_rn(x2, p));
    p = __fadd_rn(6.37261928875436e-04f,  __fmul_rn(x2, p));
    p = __fadd_rn(4.89352455891786e-03f,  __fmul_rn(x2, p));
    float num = __fmul_rn(xc, p);
    float q = __fadd_rn(1.18534705686654e-04f, __fmul_rn(x2, 1.19825839466702e-06f));
    q = __fadd_rn(2.26843463243900e-03f, __fmul_rn(x2, q));
    q = __fadd_rn(4.89352518554385e-03f, __fmul_rn(x2, q));
    float r = __fdiv_rn(num, q);
    return (fabsf(x) < 0.0004f) ? x : r;
}

// ---- fast-div version (per-sample path; ~2ulp) ----
__device__ __forceinline__ float xla_tanh_f(float x) {
    const float kClamp = 7.90531110763549805f;
    float xc = fminf(fmaxf(x, -kClamp), kClamp);
    float x2 = __fmul_rn(xc, xc);
    float p = __fadd_rn(2.00018790482477e-13f, __fmul_rn(x2, -2.76076847742355e-16f));
    p = __fadd_rn(-8.60467152213735e-11f, __fmul_rn(x2, p));
    p = __fadd_rn(5.12229709037114e-08f,  __fmul_rn(x2, p));
    p = __fadd_rn(1.48572235717979e-05f,  __fmul_rn(x2, p));
    p = __fadd_rn(6.37261928875436e-04f,  __fmul_rn(x2, p));
    p = __fadd_rn(4.89352455891786e-03f,  __fmul_rn(x2, p));
    float num = __fmul_rn(xc, p);
    float q = __fadd_rn(1.18534705686654e-04f, __fmul_rn(x2, 1.19825839466702e-06f));
    q = __fadd_rn(2.26843463243900e-03f, __fmul_rn(x2, q));
    q = __fadd_rn(4.89352518554385e-03f, __fmul_rn(x2, q));
    float r = __fdividef(num, q);
    return (fabsf(x) < 0.0004f) ? x : r;
}

__device__ __forceinline__ void fast_sc(float r, float& ps, float& pc, int& iq) {
    float qf = rintf(r * 0.636619772367581343f);
    float t = fmaf(qf, -1.57079637050628662109f, r);
    t = fmaf(qf, 4.37113900018624283e-8f, t);
    iq = ((int)qf) & 3;
    float t2 = t * t;
    float s = fmaf(t2, 2.7557314297e-06f, -1.9841270114e-04f);
    s = fmaf(t2, s, 8.3333337680e-03f);
    s = fmaf(t2, s, -1.6666667163e-01f);
    ps = fmaf(t * t2, s, t);
    float c = fmaf(t2, 2.4801587642e-05f, -1.3888889225e-03f);
    c = fmaf(t2, c, 4.1666667908e-02f);
    c = fmaf(t2, c, -0.5f);
    pc = fmaf(t2, c, 1.0f);
}

__device__ __forceinline__ float cum_base3(float c, unsigned v) {
    int msb = 31 - __clz(v);
    float r = c * __int_as_float((127 + msb) << 23);
#pragma unroll 1
    for (int k = msb - 1; k >= 3; k--) {
        if ((v >> k) & 1u)
            r = __fadd_rn(r, c * __int_as_float((127 + k) << 23));
    }
    return r;
}

__device__ __forceinline__ void compute_frame(const float* __restrict__ lg, float* dst) {
    float th0 = xla_tanh_cr(lg[0]);
    float a1 = __fmul_rn(__fmul_rn(2.0f, th0), STAB);
    float a1a = fabsf(a1);
    float th1 = xla_tanh_cr(lg[1]);
    float a2 = __fdiv_rn(__fadd_rn(__fmul_rn(__fmul_rn(__fsub_rn(2.0f, a1a), th1), STAB), a1a), 2.0f);
    dst[0] = a1; dst[1] = a2; dst[2] = lg[2]; dst[3] = lg[3]; dst[4] = lg[4];
}

// ---------------- K1: osc + env + a1/a2 interp + fused pass1 (no coeff-plane stores) ----------------
__global__ void __launch_bounds__(128) k_mainp1(
        float* __restrict__ out,
        const float* __restrict__ f0_hz,
        const float* __restrict__ durp,
        const float* __restrict__ phasep,
        const float* __restrict__ logits,
        const float* __restrict__ shpp,
        const float* __restrict__ gainp,
        const float* __restrict__ alphap) {
    __shared__ float sfr[5][5];
    __shared__ float sbp[12];

    int tid = blockIdx.x * blockDim.x + threadIdx.x;
    int b = tid >> 13;
    int c = tid & (NCH - 1);
    int s0 = c << 3;

    int BS0 = (blockIdx.x & 63) << 10;
    float bpos0 = __fmul_rn((float)BS0, POSC);
    int f_first = min((int)floorf(bpos0), 126);

    if (threadIdx.x < 5) {
        int f = f_first + threadIdx.x;
        if (f <= 127)
            compute_frame(logits + ((size_t)(b * NF + f)) * 5, sfr[threadIdx.x]);
    } else if (threadIdx.x == 5) {
        float f0 = f0_hz[b];
        sbp[0] = __fdiv_rn(f0, SRf);
        sbp[1] = phasep[b];
        float partials = __fdiv_rn(12000.0f, __fmul_rn(f0, log10f(f0)));
        sbp[2] = __fmul_rn(3.14159274101257324f, partials);
        float sh = shpp[b];
        sbp[3] = sh;
        sbp[4] = __fsub_rn(1.0f, __fmul_rn(sh, 0.5f));
        sbp[5] = gainp[b];
        sbp[6] = durp[b];
        sbp[7] = alphap[b];
        sbp[8] = __fdiv_rn(1.0f, durp[b]);
    }
    __syncthreads();

    float p_inc = sbp[0], p_phase = sbp[1], p_kk = sbp[2], p_shp = sbp[3];
    float p_sm = sbp[4], p_gain = sbp[5], p_dur = sbp[6], p_alpha = sbp[7], p_rdur = sbp[8];

    float pos0 = __fmul_rn((float)s0, POSC);
    int i0s = min((int)floorf(pos0), 126);
    int r0i = i0s - f_first;
    int r2i = min(i0s + 2, 127) - f_first;
    // only a1,a2 needed for the pass1 recurrence
    float Fa1_0 = sfr[r0i][0], Fa2_0 = sfr[r0i][1];
    float Fa1_1 = sfr[r0i + 1][0], Fa2_1 = sfr[r0i + 1][1];
    float Fa1_2 = sfr[r2i][0], Fa2_2 = sfr[r2i][1];

    float yp1 = 0.f, yp2 = 0.f, u1 = 1.f, u2 = 0.f, v1 = 0.f, v2 = 1.f;

    float tt0 = div_cr((float)s0, SRf, R48);
    bool alive = (tt0 <= p_dur);

    size_t base = (size_t)b * NS + s0;
    float4* dptr = (float4*)(out + base);
    float4* eptr = (float4*)(out + 2ull * BS * NS + base);

    float inc = p_inc;
    float i4 = inc * 4.0f, i2c = inc * 2.0f;
    float baseA = 0.0f, baseB = 0.0f;
    if (alive) {
        baseA = (s0 == 0) ? 0.0f : cum_base3(inc, (unsigned)s0);
        baseB = cum_base3(inc, (unsigned)(s0 + 8));
    }

#pragma unroll
    for (int g = 0; g < 2; g++) {
        float dry4[4], env4[4];
#pragma unroll
        for (int j = 0; j < 4; j++) {
            int jj = g * 4 + j;
            int i = s0 + jj;
            if (alive) {
                unsigned l = (unsigned)(jj + 1);
                float cum = (l < 8u) ? baseA : baseB;
                if (l & 4u)  cum = __fadd_rn(cum, i4);
                if (l & 2u)  cum = __fadd_rn(cum, i2c);
                if (l & 1u)  cum = __fadd_rn(cum, inc);
                float arg = __fadd_rn(__fmul_rn(6.28318548202514648f, cum), p_phase);
                float carg = __fmul_rn(arg, 0.5f);
                float kq = rintf(__fmul_rn(carg, 0.15915494309189535f));
                float rr = fmaf(-kq, 6.28318548202514648f, carg);
                float ps, pc; int iq;
                fast_sc(rr, ps, pc, iq);
                float shh = (iq & 1) ? pc : ps; shh = (iq & 2) ? -shh : shh;
                float chh = (iq & 1) ? ps : pc; chh = ((iq + 1) & 2) ? -chh : chh;
                float cc = chh;
                float s = 2.0f * shh * chh;

                float sq = xla_tanh_f(__fmul_rn(__fmul_rn(p_kk, s), 0.5f));
                float vco = __fmul_rn(__fmul_rn(p_sm, sq),
                                      __fadd_rn(1.0f, __fmul_rn(p_shp, cc)));

                float tt = div_cr((float)i, SRf, R48);
                float ramp = __fsub_rn(1.0f, div_cr(tt, p_dur, p_rdur));
                ramp = fminf(fmaxf(ramp, 0.001f), 1.0f);
                float env = __powf(ramp, p_alpha);
                if (!(tt <= p_dur)) env = 0.0f;
                env4[j] = env;
                dry4[j] = __fmul_rn(__fmul_rn(vco, p_gain), env);
            } else {
                env4[j] = 0.0f;
                dry4[j] = 0.0f;
            }

            float pos = __fmul_rn((float)i, POSC);
            int i0 = min((int)floorf(pos), 126);
            float frc = __fsub_rn(pos, (float)i0);
            float w0 = __fsub_rn(1.0f, frc);
            bool hi = (i0 != i0s);
            float fa1 = hi ? Fa1_1 : Fa1_0, ga1 = hi ? Fa1_2 : Fa1_1;
            float fa2 = hi ? Fa2_1 : Fa2_0, ga2 = hi ? Fa2_2 : Fa2_1;
            float a1 = __fadd_rn(__fmul_rn(fa1, w0), __fmul_rn(ga1, frc));
            float a2 = __fadd_rn(__fmul_rn(fa2, w0), __fmul_rn(ga2, frc));

            float dj = dry4[j];
            float yp = fmaf(-a1, yp1, fmaf(-a2, yp2, dj));
            float uu = fmaf(-a1, u1, -(a2 * u2));
            float vv = fmaf(-a1, v1, -(a2 * v2));
            yp2 = yp1; yp1 = yp;
            u2 = u1; u1 = uu;
            v2 = v1; v1 = vv;
        }
        dptr[g] = make_float4(dry4[0], dry4[1], dry4[2], dry4[3]);
        eptr[g] = make_float4(env4[0], env4[1], env4[2], env4[3]);
    }

    float* o = g_chunk + (size_t)tid * 6;
    o[0] = u1; o[1] = v1; o[2] = u2; o[3] = v2; o[4] = yp1; o[5] = yp2;
}

// affine compose into explicit accumulator (acc = C ∘ acc)
#define COMPOSE_ACC(c00,c01,c10,c11,r0,r1, m00,m01,m10,m11,p0,p1) do { \
    float n00 = __fmaf_rn(c00, m00, __fmul_rn(c01, m10)); \
    float n01 = __fmaf_rn(c00, m01, __fmul_rn(c01, m11)); \
    float n10 = __fmaf_rn(c10, m00, __fmul_rn(c11, m10)); \
    float n11 = __fmaf_rn(c10, m01, __fmul_rn(c11, m11)); \
    float np0 = __fadd_rn(__fmaf_rn(c00, p0, __fmul_rn(c01, p1)), r0); \
    float np1 = __fadd_rn(__fmaf_rn(c10, p0, __fmul_rn(c11, p1)), r1); \
    m00 = n00; m01 = n01; m10 = n10; m11 = n11; p0 = np0; p1 = np1; } while (0)

// ---------------- K2: per-voice parallel scan + g_frame publish ----------------
__global__ void k_scan2(const float* __restrict__ logits) {
    extern __shared__ float sm[];
    __shared__ float wtot[8 * 6];
    __shared__ float wpre[8 * 6];
    int b = blockIdx.x;
    int tid = threadIdx.x;

    const float* raw = g_chunk + (size_t)b * NCH * 6;
    for (int idx = tid; idx < NCH * 6; idx += blockDim.x) {
        int chunk = idx / 6;
        int field = idx - chunk * 6;
        int w = chunk >> 10;
        int chr = chunk & 1023;
        int swp = ((chr & 31) << 5) | (chr >> 5);
        sm[((w << 10) + swp) * 7 + field] = raw[idx];
    }
    if (tid >= 256 && tid < 384) {
        int f = tid - 256;
        float dst[5];
        compute_frame(logits + ((size_t)(b * NF + f)) * 5, dst);
        g_frame[(b * NF + f) * 2]     = make_float4(dst[0], dst[1], dst[2], dst[3]);
        g_frame[(b * NF + f) * 2 + 1] = make_float4(dst[4], 0.f, 0.f, 0.f);
    }
    __syncthreads();

    float m00 = 1.f, m01 = 0.f, m10 = 0.f, m11 = 1.f, p0 = 0.f, p1 = 0.f;
    int w = tid >> 5, lane = tid & 31;
    if (tid < 256) {
        const float* rbase = &sm[(w << 10) * 7 + lane * 7];
#pragma unroll 1
        for (int c = 0; c < 32; c++) {
            const float* rec = rbase + (c << 5) * 7;
            COMPOSE_ACC(rec[0], rec[1], rec[2], rec[3], rec[4], rec[5],
                        m00, m01, m10, m11, p0, p1);
        }
#pragma unroll
        for (int d = 1; d < 32; d <<= 1) {
            float e00 = __shfl_up_sync(0xffffffffu, m00, d);
            float e01 = __shfl_up_sync(0xffffffffu, m01, d);
            float e10 = __shfl_up_sync(0xffffffffu, m10, d);
            float e11 = __shfl_up_sync(0xffffffffu, m11, d);
            float ep0 = __shfl_up_sync(0xffffffffu, p0, d);
            float ep1 = __shfl_up_sync(0xffffffffu, p1, d);
            if (lane >= d) {
                float n00 = __fmaf_rn(m00, e00, __fmul_rn(m01, e10));
                float n01 = __fmaf_rn(m00, e01, __fmul_rn(m01, e11));
                float n10 = __fmaf_rn(m10, e00, __fmul_rn(m11, e10));
                float n11 = __fmaf_rn(m10, e01, __fmul_rn(m11, e11));
                float np0 = __fadd_rn(__fmaf_rn(m00, ep0, __fmul_rn(m01, ep1)), p0);
                float np1 = __fadd_rn(__fmaf_rn(m10, ep0, __fmul_rn(m11, ep1)), p1);
                m00 = n00; m01 = n01; m10 = n10; m11 = n11; p0 = np0; p1 = np1;
            }
        }
        if (lane == 31) {
            wtot[w * 6 + 0] = m00; wtot[w * 6 + 1] = m01; wtot[w * 6 + 2] = m10;
            wtot[w * 6 + 3] = m11; wtot[w * 6 + 4] = p0;  wtot[w * 6 + 5] = p1;
        }
    }
    __syncthreads();
    if (tid == 0) {
        float q00 = 1.f, q01 = 0.f, q10 = 0.f, q11 = 1.f, qp0 = 0.f, qp1 = 0.f;
#pragma unroll
        for (int ww = 0; ww < 8; ww++) {
            wpre[ww * 6 + 0] = q00; wpre[ww * 6 + 1] = q01; wpre[ww * 6 + 2] = q10;
            wpre[ww * 6 + 3] = q11; wpre[ww * 6 + 4] = qp0; wpre[ww * 6 + 5] = qp1;
            COMPOSE_ACC(wtot[ww * 6 + 0], wtot[ww * 6 + 1], wtot[ww * 6 + 2],
                        wtot[ww * 6 + 3], wtot[ww * 6 + 4], wtot[ww * 6 + 5],
                        q00, q01, q10, q11, qp0, qp1);
        }
    }
    __syncthreads();
    if (tid < 256) {
        float e00 = __shfl_up_sync(0xffffffffu, m00, 1);
        float e01 = __shfl_up_sync(0xffffffffu, m01, 1);
        float e10 = __shfl_up_sync(0xffffffffu, m10, 1);
        float e11 = __shfl_up_sync(0xffffffffu, m11, 1);
        float ep0 = __shfl_up_sync(0xffffffffu, p0, 1);
        float ep1 = __shfl_up_sync(0xffffffffu, p1, 1);
        if (lane == 0) { e00 = 1.f; e01 = 0.f; e10 = 0.f; e11 = 1.f; ep0 = 0.f; ep1 = 0.f; }
        float Pp0 = wpre[w * 6 + 4], Pp1 = wpre[w * 6 + 5];
        float s0 = __fadd_rn(__fmaf_rn(e00, Pp0, __fmul_rn(e01, Pp1)), ep0);
        float s1 = __fadd_rn(__fmaf_rn(e10, Pp0, __fmul_rn(e11, Pp1)), ep1);

        const float* rbase = &sm[(w << 10) * 7 + lane * 7];
        int cbase = (b << 13) + tid * 32;
#pragma unroll 1
        for (int c = 0; c < 32; c++) {
            g_init[cbase + c] = make_float2(s0, s1);
            const float* rec = rbase + (c << 5) * 7;
            float ns0 = __fadd_rn(__fmaf_rn(rec[0], s0, __fmul_rn(rec[1], s1)), rec[4]);
            float ns1 = __fadd_rn(__fmaf_rn(rec[2], s0, __fmul_rn(rec[3], s1)), rec[5]);
            s0 = ns0; s1 = ns1;
        }
    }
}

// ---------------- K3: pass 2 — coeffs (compute + STORE planes) + IIR + FIR + tanh ----------------
__global__ void __launch_bounds__(128) k_pass2(float* __restrict__ out,
                                               const float* __restrict__ distp) {
    int tid = blockIdx.x * blockDim.x + threadIdx.x;
    if (tid >= BS * NCH) return;
    int b = tid >> 13;
    int c = tid & (NCH - 1);
    int s0 = c << 3;
    size_t base = (size_t)b * NS + s0;
    const float* dry = out + base;
    float* w_wet = out + 1ull * BS * NS + base;
    float* w_yab = out + 3ull * BS * NS + base;
    float* w_ya = out + 10ull * BS * NS + base;
    float4* aptr = (float4*)(out + 4ull * BS * NS + base * 3);
    float4* bptr = (float4*)(out + 7ull * BS * NS + base * 3);

    float pos0 = __fmul_rn((float)s0, POSC);
    int i0s = min((int)floorf(pos0), 126);
    int i2x = min(i0s + 2, 127);
    float4 F0a = g_frame[(b * NF + i0s) * 2],     F0b = g_frame[(b * NF + i0s) * 2 + 1];
    float4 F1a = g_frame[(b * NF + i0s + 1) * 2], F1b = g_frame[(b * NF + i0s + 1) * 2 + 1];
    float4 F2a = g_frame[(b * NF + i2x) * 2],     F2b = g_frame[(b * NF + i2x) * 2 + 1];

    float2 ini = g_init[tid];
    float y1 = ini.x, y2 = ini.y;
    float dg = distp[b];

#pragma unroll
    for (int g = 0; g < 2; g++) {
        float4 xq = ((const float4*)dry)[g];
        float xs[4] = {xq.x, xq.y, xq.z, xq.w};
        float ya[4], yb[4], wt[4];
        float a1v[4], a2v[4], b0v[4], b1v[4], b2v[4];
#pragma unroll
        for (int j = 0; j < 4; j++) {
            int i = s0 + g * 4 + j;
            float pos = __fmul_rn((float)i, POSC);
            int i0 = min((int)floorf(pos), 126);
            float frc = __fsub_rn(pos, (float)i0);
            float w0 = __fsub_rn(1.0f, frc);
            bool hi = (i0 != i0s);
            float4 fA = hi ? F1a : F0a;
            float4 fB = hi ? F1b : F0b;
            float4 gA = hi ? F2a : F1a;
            float4 gB = hi ? F2b : F1b;
            float a1 = __fadd_rn(__fmul_rn(fA.x, w0), __fmul_rn(gA.x, frc));
            float a2 = __fadd_rn(__fmul_rn(fA.y, w0), __fmul_rn(gA.y, frc));
            float c0 = __fadd_rn(__fmul_rn(fA.z, w0), __fmul_rn(gA.z, frc));
            float c1 = __fadd_rn(__fmul_rn(fA.w, w0), __fmul_rn(gA.w, frc));
            float c2 = __fadd_rn(__fmul_rn(fB.x, w0), __fmul_rn(gB.x, frc));
            a1v[j] = a1; a2v[j] = a2; b0v[j] = c0; b1v[j] = c1; b2v[j] = c2;

            float y = __fsub_rn(__fsub_rn(xs[j], __fmul_rn(a1, y1)), __fmul_rn(a2, y2));
            float v = __fadd_rn(__fadd_rn(__fmul_rn(c0, y), __fmul_rn(c1, y1)),
                                __fmul_rn(c2, y2));
            ya[j] = y; yb[j] = v;
            wt[j] = xla_tanh_f(__fmul_rn(v, dg));
            y2 = y1; y1 = y;
        }
        ((float4*)w_ya)[g] = make_float4(ya[0], ya[1], ya[2], ya[3]);
        ((float4*)w_yab)[g] = make_float4(yb[0], yb[1], yb[2], yb[3]);
        ((float4*)w_wet)[g] = make_float4(wt[0], wt[1], wt[2], wt[3]);
        aptr[3 * g + 0] = make_float4(1.0f, a1v[0], a2v[0], 1.0f);
        aptr[3 * g + 1] = make_float4(a1v[1], a2v[1], 1.0f, a1v[2]);
        aptr[3 * g + 2] = make_float4(a2v[2], 1.0f, a1v[3], a2v[3]);
        bptr[3 * g + 0] = make_float4(b0v[0], b1v[0], b2v[0], b0v[1]);
        bptr[3 * g + 1] = make_float4(b1v[1], b2v[1], b0v[2], b1v[2]);
        bptr[3 * g + 2] = make_float4(b2v[2], b0v[3], b1v[3], b2v[3]);
    }
}

extern "C" void kernel_launch(void* const* d_in, const int* in_sizes, int n_in,
                              void* d_out, int out_size) {
    const float* f0_hz = (const float*)d_in[0];
    const float* note_on = (const float*)d_in[1];
    const float* phase = (const float*)d_in[2];
    const float* logits = (const float*)d_in[3];
    const float* osc_shape = (const float*)d_in[4];
    const float* osc_gain = (const float*)d_in[5];
    const float* dist_gain = (const float*)d_in[6];
    const float* learned_alpha = (const float*)d_in[7];
    float* out = (float*)d_out;

    static int smem_set = 0;
    const int scan_smem = NCH * 7 * sizeof(float);   // 229376 B dynamic
    if (!smem_set) {
        cudaFuncSetAttribute(k_scan2, cudaFuncAttributeMaxDynamicSharedMemorySize, scan_smem);
        smem_set = 1;
    }

    k_mainp1<<<(BS * NCH + 127) / 128, 128>>>(out, f0_hz, note_on, phase, logits,
                                              osc_shape, osc_gain, learned_alpha);
    k_scan2<<<BS, 1024, scan_smem>>>(logits);
    k_pass2<<<(BS * NCH + 127) / 128, 128>>>(out, dist_gain);
}